// round 2
// baseline (speedup 1.0000x reference)
#include <cuda_runtime.h>
#include <cuda_bf16.h>
#include <math.h>

// ---------------- model constants ----------------
#define B_     64
#define NPATCH 196
#define NT     197          // tokens per image
#define DIM    512
#define HEADS  8
#define HD     64
#define MLPD   2048
#define CPP    768          // C*P*P = 3*16*16
#define T_TOK  (B_*NT)      // 12608
#define T_PAT  (B_*NPATCH)  // 12544
#define MP     12672        // padded token rows: 128*99

// ---------------- scratch (device globals: zero-init, allocation-free) ----------------
__device__ float g_xp [T_PAT * CPP];     // patchified pixels   [12544, 768]
__device__ float g_emb[T_PAT * DIM];     // patch embeddings    [12544, 512]
__device__ float g_x  [MP * DIM];        // activations         [12672, 512]
__device__ float g_y  [MP * DIM];        // pre-LN buffer
__device__ float g_qkv[MP * 3 * DIM];    // qkv                 [12672, 1536]
__device__ float g_ctx[MP * DIM];        // attention context
__device__ float g_h  [MP * MLPD];       // mlp hidden          [12672, 2048]

// ---------------- patchify: img[B,3,224,224] -> xp[12544,768] ----------------
__global__ void patchify_kernel(const float* __restrict__ img, float* __restrict__ xp) {
    int idx = blockIdx.x * blockDim.x + threadIdx.x;
    if (idx >= T_PAT * CPP) return;
    int f   = idx % CPP;
    int row = idx / CPP;
    int b = row / NPATCH, p = row % NPATCH;
    int gh = p / 14, gw = p % 14;
    int c  = f % 3;
    int pp = f / 3;
    int p1 = pp >> 4, p2 = pp & 15;
    xp[idx] = img[(((size_t)(b * 3 + c)) * 224 + gh * 16 + p1) * 224 + gw * 16 + p2];
}

// ---------------- assemble: cls + patch emb + pos ----------------
__global__ void assemble_kernel(const float* __restrict__ emb,
                                const float* __restrict__ cls,
                                const float* __restrict__ pos,
                                float* __restrict__ x) {
    int idx = blockIdx.x * blockDim.x + threadIdx.x;
    if (idx >= T_TOK * DIM) return;
    int d = idx & (DIM - 1);
    int t = idx >> 9;
    int b = t / NT, n = t % NT;
    float v = (n == 0) ? cls[d] : emb[((size_t)(b * NPATCH + n - 1)) * DIM + d];
    x[idx] = v + pos[n * DIM + d];
}

// ---------------- CLS slice ----------------
__global__ void clsout_kernel(const float* __restrict__ x, float* __restrict__ out) {
    int idx = blockIdx.x * blockDim.x + threadIdx.x;
    if (idx >= B_ * DIM) return;
    int b = idx >> 9, d = idx & (DIM - 1);
    out[idx] = x[((size_t)b * NT) * DIM + d];
}

// ---------------- SGEMM: C[M,N] = A[M,K] @ W[N,K]^T + bias (+res / gelu) ----------------
// 128x128 tile, BK=8, 256 threads, 8x8 per thread (2x2 groups of 4x4 at +64 offsets).
__device__ __forceinline__ float gelu_exact(float v) {
    return 0.5f * v * (1.0f + erff(v * 0.70710678118654752f));
}

template <int EPI>   // 0: bias   1: bias+residual   2: bias+gelu
__global__ void __launch_bounds__(256)
sgemm_kernel(const float* __restrict__ A, const float* __restrict__ W,
             const float* __restrict__ bias, const float* __restrict__ res,
             float* __restrict__ C, int M, int N, int K) {
    __shared__ float As[8][128];
    __shared__ float Bs[8][128];
    const int bm = blockIdx.y * 128;
    const int bn = blockIdx.x * 128;
    const int tid = threadIdx.x;
    const int tx = tid & 15;
    const int ty = tid >> 4;
    const int lrow = tid >> 1;          // 0..127
    const int lk   = (tid & 1) * 4;     // 0 or 4
    const float* Aptr = A + (size_t)(bm + lrow) * K + lk;
    const float* Wptr = W + (size_t)(bn + lrow) * K + lk;

    float acc[8][8];
#pragma unroll
    for (int i = 0; i < 8; i++)
#pragma unroll
        for (int j = 0; j < 8; j++) acc[i][j] = 0.f;

    for (int k0 = 0; k0 < K; k0 += 8) {
        float4 av = *(const float4*)(Aptr + k0);
        float4 bv = *(const float4*)(Wptr + k0);
        As[lk + 0][lrow] = av.x; As[lk + 1][lrow] = av.y;
        As[lk + 2][lrow] = av.z; As[lk + 3][lrow] = av.w;
        Bs[lk + 0][lrow] = bv.x; Bs[lk + 1][lrow] = bv.y;
        Bs[lk + 2][lrow] = bv.z; Bs[lk + 3][lrow] = bv.w;
        __syncthreads();
#pragma unroll
        for (int k = 0; k < 8; k++) {
            float a[8], b[8];
            *(float4*)(a)     = *(const float4*)(&As[k][ty * 4]);
            *(float4*)(a + 4) = *(const float4*)(&As[k][64 + ty * 4]);
            *(float4*)(b)     = *(const float4*)(&Bs[k][tx * 4]);
            *(float4*)(b + 4) = *(const float4*)(&Bs[k][64 + tx * 4]);
#pragma unroll
            for (int i = 0; i < 8; i++)
#pragma unroll
                for (int j = 0; j < 8; j++)
                    acc[i][j] = fmaf(a[i], b[j], acc[i][j]);
        }
        __syncthreads();
    }

#pragma unroll
    for (int i = 0; i < 8; i++) {
        int row = bm + ((i < 4) ? (ty * 4 + i) : (64 + ty * 4 + i - 4));
#pragma unroll
        for (int jg = 0; jg < 2; jg++) {
            int col0 = bn + jg * 64 + tx * 4;
            float4 bb = *(const float4*)(bias + col0);
            float4 v;
            v.x = acc[i][jg * 4 + 0] + bb.x;
            v.y = acc[i][jg * 4 + 1] + bb.y;
            v.z = acc[i][jg * 4 + 2] + bb.z;
            v.w = acc[i][jg * 4 + 3] + bb.w;
            if (EPI == 1) {
                float4 r = *(const float4*)(res + (size_t)row * N + col0);
                v.x += r.x; v.y += r.y; v.z += r.z; v.w += r.w;
            }
            if (EPI == 2) {
                v.x = gelu_exact(v.x); v.y = gelu_exact(v.y);
                v.z = gelu_exact(v.z); v.w = gelu_exact(v.w);
            }
            *(float4*)(C + (size_t)row * N + col0) = v;
        }
    }
}

// ---------------- attention: one block per (b, h) ----------------
// smem layout (floats): Qs[197*64] | Vs[197*64] | Ks[197*65] | sbuf[8*197]
// Qs,Vs at multiples of 4 floats (16B aligned, float2/float4-safe);
// Ks keeps stride 65 for conflict-free per-row dot products.
#define ATTN_SMEM ((NT * 64 + NT * 64 + NT * 65 + 8 * NT) * (int)sizeof(float))

__global__ void __launch_bounds__(256)
attn_kernel(const float* __restrict__ qkv, float* __restrict__ ctx) {
    extern __shared__ float sm[];
    float* Qs = sm;                  // offset 0
    float* Vs = Qs + NT * 64;        // offset 12608 (multiple of 4 -> 16B aligned)
    float* Ks = Vs + NT * 64;        // offset 25216 (scalar access, stride 65)
    float* sb = Ks + NT * 65;        // scores, scalar access
    int b = blockIdx.x >> 3, h = blockIdx.x & 7;
    const float* base = qkv + (size_t)b * NT * (3 * DIM) + h * HD;
    int tid = threadIdx.x;
    for (int i = tid; i < NT * 64; i += 256) {
        int n = i >> 6, d = i & 63;
        const float* p = base + (size_t)n * (3 * DIM) + d;
        Qs[i] = p[0];
        Ks[n * 65 + d] = p[DIM];
        Vs[i] = p[2 * DIM];
    }
    __syncthreads();
    int wid = tid >> 5, lane = tid & 31;
    float* srow = sb + wid * NT;
    const float2* V2 = (const float2*)Vs;

    for (int row = wid; row < NT; row += 8) {
        const float* q = Qs + row * 64;
        float mx = -1e30f;
        for (int m = lane; m < NT; m += 32) {
            const float* kr = Ks + m * 65;
            float s = 0.f;
#pragma unroll
            for (int d = 0; d < 64; d++) s = fmaf(q[d], kr[d], s);
            s *= 0.125f;                       // 1/sqrt(64)
            srow[m] = s;
            mx = fmaxf(mx, s);
        }
#pragma unroll
        for (int o = 16; o; o >>= 1) mx = fmaxf(mx, __shfl_xor_sync(0xffffffffu, mx, o));
        float sum = 0.f;
        for (int m = lane; m < NT; m += 32) {
            float e = __expf(srow[m] - mx);
            srow[m] = e;
            sum += e;
        }
#pragma unroll
        for (int o = 16; o; o >>= 1) sum += __shfl_xor_sync(0xffffffffu, sum, o);
        float inv = 1.f / sum;
        __syncwarp();
        float ax = 0.f, ay = 0.f;
        for (int m = 0; m < NT; m++) {
            float p = srow[m];
            float2 v = V2[m * 32 + lane];
            ax = fmaf(p, v.x, ax);
            ay = fmaf(p, v.y, ay);
        }
        float* o = ctx + ((size_t)(b * NT + row)) * DIM + h * HD + lane * 2;
        o[0] = ax * inv;
        o[1] = ay * inv;
        __syncwarp();   // protect srow reuse across row iterations
    }
}

// ---------------- layernorm: one block (128 threads) per row of 512 ----------------
__global__ void __launch_bounds__(128)
ln_kernel(const float* __restrict__ in, const float* __restrict__ w,
          const float* __restrict__ bp, float* __restrict__ out) {
    int row = blockIdx.x;
    int t = threadIdx.x;
    float4 v = ((const float4*)(in + (size_t)row * DIM))[t];
    float s  = v.x + v.y + v.z + v.w;
    float sq = v.x * v.x + v.y * v.y + v.z * v.z + v.w * v.w;
#pragma unroll
    for (int o = 16; o; o >>= 1) {
        s  += __shfl_xor_sync(0xffffffffu, s, o);
        sq += __shfl_xor_sync(0xffffffffu, sq, o);
    }
    __shared__ float ss[4], ssq[4];
    int wid = t >> 5, lane = t & 31;
    if (lane == 0) { ss[wid] = s; ssq[wid] = sq; }
    __syncthreads();
    s  = ss[0] + ss[1] + ss[2] + ss[3];
    sq = ssq[0] + ssq[1] + ssq[2] + ssq[3];
    float mean = s * (1.f / 512.f);
    float var  = sq * (1.f / 512.f) - mean * mean;
    float r = rsqrtf(var + 1e-5f);
    float4 wv = ((const float4*)w)[t];
    float4 bv = ((const float4*)bp)[t];
    float4 o;
    o.x = (v.x - mean) * r * wv.x + bv.x;
    o.y = (v.y - mean) * r * wv.y + bv.y;
    o.z = (v.z - mean) * r * wv.z + bv.z;
    o.w = (v.w - mean) * r * wv.w + bv.w;
    ((float4*)(out + (size_t)row * DIM))[t] = o;
}

// ---------------- host launcher ----------------
extern "C" void kernel_launch(void* const* d_in, const int* in_sizes, int n_in,
                              void* d_out, int out_size) {
    (void)in_sizes; (void)n_in; (void)out_size;
    const float* img    = (const float*)d_in[0];
    const float* pw     = (const float*)d_in[1];
    const float* pb     = (const float*)d_in[2];
    const float* cls    = (const float*)d_in[3];
    const float* pos    = (const float*)d_in[4];
    const float* ipw    = (const float*)d_in[5];
    const float* ipb    = (const float*)d_in[6];
    const float* opw    = (const float*)d_in[7];
    const float* opb    = (const float*)d_in[8];
    const float* ln1w   = (const float*)d_in[9];
    const float* ln1b   = (const float*)d_in[10];
    const float* fc1w   = (const float*)d_in[11];
    const float* fc1b   = (const float*)d_in[12];
    const float* fc2w   = (const float*)d_in[13];
    const float* fc2b   = (const float*)d_in[14];
    const float* ln2w   = (const float*)d_in[15];
    const float* ln2b   = (const float*)d_in[16];
    float* out = (float*)d_out;

    float *xp, *emb, *x, *y, *qkv, *ctx, *h;
    cudaGetSymbolAddress((void**)&xp,  g_xp);
    cudaGetSymbolAddress((void**)&emb, g_emb);
    cudaGetSymbolAddress((void**)&x,   g_x);
    cudaGetSymbolAddress((void**)&y,   g_y);
    cudaGetSymbolAddress((void**)&qkv, g_qkv);
    cudaGetSymbolAddress((void**)&ctx, g_ctx);
    cudaGetSymbolAddress((void**)&h,   g_h);

    cudaFuncSetAttribute(attn_kernel, cudaFuncAttributeMaxDynamicSharedMemorySize, ATTN_SMEM);

    // patch embed
    {
        int n = T_PAT * CPP;
        patchify_kernel<<<(n + 255) / 256, 256>>>(img, xp);
        sgemm_kernel<0><<<dim3(DIM / 128, T_PAT / 128), 256>>>(xp, pw, pb, nullptr, emb,
                                                               T_PAT, DIM, CPP);
        int m = T_TOK * DIM;
        assemble_kernel<<<(m + 255) / 256, 256>>>(emb, cls, pos, x);
    }

    for (int i = 0; i < 6; i++) {
        const float* ipw_i  = ipw  + (size_t)i * 3 * DIM * DIM;
        const float* ipb_i  = ipb  + (size_t)i * 3 * DIM;
        const float* opw_i  = opw  + (size_t)i * DIM * DIM;
        const float* opb_i  = opb  + (size_t)i * DIM;
        const float* fc1w_i = fc1w + (size_t)i * MLPD * DIM;
        const float* fc1b_i = fc1b + (size_t)i * MLPD;
        const float* fc2w_i = fc2w + (size_t)i * DIM * MLPD;
        const float* fc2b_i = fc2b + (size_t)i * DIM;

        // qkv = x @ Wqkv^T + b
        sgemm_kernel<0><<<dim3(3 * DIM / 128, MP / 128), 256>>>(x, ipw_i, ipb_i, nullptr,
                                                                qkv, MP, 3 * DIM, DIM);
        // attention
        attn_kernel<<<B_ * HEADS, 256, ATTN_SMEM>>>(qkv, ctx);
        // out proj + residual
        sgemm_kernel<1><<<dim3(DIM / 128, MP / 128), 256>>>(ctx, opw_i, opb_i, x,
                                                            y, MP, DIM, DIM);
        // LN1
        ln_kernel<<<T_TOK, 128>>>(y, ln1w + i * DIM, ln1b + i * DIM, x);
        // fc1 + gelu
        sgemm_kernel<2><<<dim3(MLPD / 128, MP / 128), 256>>>(x, fc1w_i, fc1b_i, nullptr,
                                                             h, MP, MLPD, DIM);
        // fc2 + residual
        sgemm_kernel<1><<<dim3(DIM / 128, MP / 128), 256>>>(h, fc2w_i, fc2b_i, x,
                                                            y, MP, DIM, MLPD);
        // LN2
        ln_kernel<<<T_TOK, 128>>>(y, ln2w + i * DIM, ln2b + i * DIM, x);
    }

    // CLS slice
    {
        int n = B_ * DIM;
        clsout_kernel<<<(n + 255) / 256, 256>>>(x, out);
    }
}

// round 4
// speedup vs baseline: 1.7401x; 1.7401x over previous
#include <cuda_runtime.h>
#include <cuda_bf16.h>
#include <cuda.h>
#include <math.h>
#include <stdint.h>

// ---------------- model constants ----------------
#define B_     64
#define NPATCH 196
#define NT     197
#define DIM    512
#define HEADS  8
#define HD     64
#define MLPD   2048
#define CPP    768
#define T_TOK  (B_*NT)      // 12608
#define T_PAT  (B_*NPATCH)  // 12544
#define MP2    12800        // padded rows: 128*100

// ---------------- helpers ----------------
__device__ __forceinline__ uint32_t smem_to_u32(const void* p) {
    uint32_t a;
    asm("{ .reg .u64 t; cvta.to.shared.u64 t, %1; cvt.u32.u64 %0, t; }" : "=r"(a) : "l"(p));
    return a;
}
#define SWZ128(o) ((o) ^ (((o) >> 3) & 0x70))

__device__ __forceinline__ void cp16(uint32_t dst, const void* src) {
    asm volatile("cp.async.cg.shared.global [%0], [%1], 16;" :: "r"(dst), "l"(src));
}
#define CP_COMMIT() asm volatile("cp.async.commit_group;" ::: "memory")
#define CP_WAIT(n)  asm volatile("cp.async.wait_group %0;" :: "n"(n) : "memory")

#define LDMATRIX_X4(r, addr) \
    asm volatile("ldmatrix.sync.aligned.m8n8.x4.shared.b16 {%0,%1,%2,%3}, [%4];" \
        : "=r"((r)[0]), "=r"((r)[1]), "=r"((r)[2]), "=r"((r)[3]) : "r"(addr))

__device__ __forceinline__ void mma_bf16(float* c, const uint32_t* a, uint32_t b0, uint32_t b1) {
    asm volatile(
        "mma.sync.aligned.m16n8k16.row.col.f32.bf16.bf16.f32 "
        "{%0,%1,%2,%3}, {%4,%5,%6,%7}, {%8,%9}, {%0,%1,%2,%3};"
        : "+f"(c[0]), "+f"(c[1]), "+f"(c[2]), "+f"(c[3])
        : "r"(a[0]), "r"(a[1]), "r"(a[2]), "r"(a[3]), "r"(b0), "r"(b1));
}

// ---------------- scratch (device globals: zero-init, allocation-free) ----------------
__device__ float g_x   [MP2 * DIM];
__device__ float g_y   [MP2 * DIM];
__device__ float g_qkv [MP2 * 3 * DIM];
__device__ float g_emb [MP2 * DIM];
__device__ __align__(16) __nv_bfloat16 g_xps  [MP2 * 2 * CPP];
__device__ __align__(16) __nv_bfloat16 g_xs   [MP2 * 2 * DIM];
__device__ __align__(16) __nv_bfloat16 g_cs   [MP2 * 2 * DIM];
__device__ __align__(16) __nv_bfloat16 g_hs   [MP2 * 2 * MLPD];
__device__ __align__(16) __nv_bfloat16 g_pws  [DIM * 2 * CPP];
__device__ __align__(16) __nv_bfloat16 g_ipws [6 * 3 * DIM * 2 * DIM];
__device__ __align__(16) __nv_bfloat16 g_opws [6 * DIM * 2 * DIM];
__device__ __align__(16) __nv_bfloat16 g_fc1ws[6 * MLPD * 2 * DIM];
__device__ __align__(16) __nv_bfloat16 g_fc2ws[6 * DIM * 2 * MLPD];

__device__ __forceinline__ void split_store(__nv_bfloat16* dst, size_t rb, int K, int c, float v) {
    __nv_bfloat16 hi = __float2bfloat16(v);
    float lo = v - __bfloat162float(hi);
    dst[rb + c]     = hi;
    dst[rb + K + c] = __float2bfloat16(lo);
}

__global__ void wsplit_kernel(const float* __restrict__ src, __nv_bfloat16* __restrict__ dst,
                              int K, int total) {
    int idx = blockIdx.x * blockDim.x + threadIdx.x;
    if (idx >= total) return;
    int n = idx / K, c = idx % K;
    split_store(dst, (size_t)n * 2 * K, K, c, src[idx]);
}

__global__ void patchify_kernel(const float* __restrict__ img, __nv_bfloat16* __restrict__ xps) {
    int idx = blockIdx.x * blockDim.x + threadIdx.x;
    if (idx >= T_PAT * CPP) return;
    int f   = idx % CPP;
    int row = idx / CPP;
    int b = row / NPATCH, p = row % NPATCH;
    int gh = p / 14, gw = p % 14;
    int c  = f % 3;
    int pp = f / 3;
    int p1 = pp >> 4, p2 = pp & 15;
    float v = img[(((size_t)(b * 3 + c)) * 224 + gh * 16 + p1) * 224 + gw * 16 + p2];
    split_store(xps, (size_t)row * (2 * CPP), CPP, f, v);
}

__global__ void assemble_kernel(const float* __restrict__ emb,
                                const float* __restrict__ cls,
                                const float* __restrict__ pos,
                                float* __restrict__ x, __nv_bfloat16* __restrict__ xs) {
    int idx = blockIdx.x * blockDim.x + threadIdx.x;
    if (idx >= T_TOK * DIM) return;
    int d = idx & (DIM - 1);
    int t = idx >> 9;
    int b = t / NT, n = t % NT;
    float v = (n == 0) ? cls[d] : emb[((size_t)(b * NPATCH + n - 1)) * DIM + d];
    v += pos[n * DIM + d];
    x[idx] = v;
    split_store(xs, (size_t)t * (2 * DIM), DIM, d, v);
}

__global__ void clsout_kernel(const float* __restrict__ x, float* __restrict__ out) {
    int idx = blockIdx.x * blockDim.x + threadIdx.x;
    if (idx >= B_ * DIM) return;
    int b = idx >> 9, d = idx & (DIM - 1);
    out[idx] = x[((size_t)b * NT) * DIM + d];
}

__device__ __forceinline__ float gelu_exact(float v) {
    return 0.5f * v * (1.0f + erff(v * 0.70710678118654752f));
}

// =====================================================================
// HMMA GEMM: C[M,N] = A[M,K](split hi|lo) @ W[N,K](split)^T, 3-term bf16.
// CTA 128x128, BK=64 bf16 per chunk, virtual chunks NC=3K/64 (remap).
// 8 warps: 4(m) x 2(n), warp tile m32 x n64, mma.m16n8k16.
// EPI 0: fp32 bias   1: fp32 bias+res   2: split-bf16 gelu(bias+acc)
// =====================================================================
#define GEMM_SMEM_BYTES 65536

// fill one 128x64 bf16 tile (128B rows, SW128) via cp.async
__device__ __forceinline__ void prefetch_tile(const __nv_bfloat16* __restrict__ G,
                                              int K2, uint32_t sbase, int tid) {
#pragma unroll
    for (int r = 0; r < 4; r++) {
        int i = tid + r * 256;
        int row = i >> 3, seg = i & 7;
        cp16(sbase + SWZ128(row * 128 + seg * 16), G + (size_t)row * K2 + seg * 8);
    }
}

template <int EPI>
__global__ void __launch_bounds__(256, 1)
mma_gemm_kernel(const __nv_bfloat16* __restrict__ A, const __nv_bfloat16* __restrict__ W,
                const float* __restrict__ bias, const float* __restrict__ res,
                float* __restrict__ Cf, __nv_bfloat16* __restrict__ Cs,
                int K, int N, int Kout) {
    extern __shared__ char smc[];
    const uint32_t sb = smem_to_u32(smc);
    const uint32_t sA[2] = {sb, sb + 16384};
    const uint32_t sB[2] = {sb + 32768, sb + 49152};
    const int tid = threadIdx.x, wid = tid >> 5, lane = tid & 31;
    const int bm = blockIdx.y * 128, bn = blockIdx.x * 128;
    const int K2 = 2 * K;
    const int NCk = K >> 6;
    const int NC = 3 * NCk;
    const int mbase = (wid >> 1) * 32;
    const int nbase = (wid & 1) * 64;

    float acc[2][8][4];
#pragma unroll
    for (int mt = 0; mt < 2; mt++)
#pragma unroll
        for (int ng = 0; ng < 8; ng++)
#pragma unroll
            for (int r = 0; r < 4; r++) acc[mt][ng][r] = 0.f;

    const __nv_bfloat16* Abase = A + (size_t)bm * K2;
    const __nv_bfloat16* Bbase = W + (size_t)bn * K2;

    // prefetch chunk 0
    prefetch_tile(Abase, K2, sA[0], tid);
    prefetch_tile(Bbase, K2, sB[0], tid);
    CP_COMMIT();

    // ldmatrix lane addressing (within a 128x64 tile, 128B rows)
    const int lrow8 = (lane & 7) + ((lane >> 3) & 1) * 8;  // row within 16-block
    const int lkoff = (lane >> 4) * 16;                    // 8 bf16 = 16 bytes

    for (int c = 0; c < NC; c++) {
        const int buf = c & 1;
        if (c + 1 < NC) {
            int cn = c + 1;
            int ca = (cn < 2 * NCk) ? cn : (cn - 2 * NCk);
            int cb = (cn < NCk) ? cn : (cn - NCk);
            prefetch_tile(Abase + ca * 64, K2, sA[buf ^ 1], tid);
            prefetch_tile(Bbase + cb * 64, K2, sB[buf ^ 1], tid);
            CP_COMMIT();
            CP_WAIT(1);
        } else {
            CP_WAIT(0);
        }
        __syncthreads();

#pragma unroll
        for (int s = 0; s < 4; s++) {
            uint32_t af[2][4], bf[4][4];
#pragma unroll
            for (int mt = 0; mt < 2; mt++) {
                int row = mbase + mt * 16 + lrow8;
                LDMATRIX_X4(af[mt], sA[buf] + SWZ128(row * 128 + s * 32 + lkoff));
            }
#pragma unroll
            for (int ng2 = 0; ng2 < 4; ng2++) {
                int row = nbase + ng2 * 16 + lrow8;
                LDMATRIX_X4(bf[ng2], sB[buf] + SWZ128(row * 128 + s * 32 + lkoff));
            }
#pragma unroll
            for (int mt = 0; mt < 2; mt++)
#pragma unroll
                for (int ng2 = 0; ng2 < 4; ng2++) {
                    mma_bf16(acc[mt][ng2 * 2],     af[mt], bf[ng2][0], bf[ng2][2]);
                    mma_bf16(acc[mt][ng2 * 2 + 1], af[mt], bf[ng2][1], bf[ng2][3]);
                }
        }
        __syncthreads();
    }

    // ---- epilogue: direct fragment stores ----
    const int qr = lane >> 2;          // 0..7
    const int qc = (lane & 3) * 2;     // 0,2,4,6
#pragma unroll
    for (int mt = 0; mt < 2; mt++) {
#pragma unroll
        for (int ng = 0; ng < 8; ng++) {
            const int col = bn + nbase + ng * 8 + qc;
            const float2 bb = *(const float2*)(bias + col);
#pragma unroll
            for (int half = 0; half < 2; half++) {
                const int row = bm + mbase + mt * 16 + qr + half * 8;
                float v0 = acc[mt][ng][half * 2 + 0] + bb.x;
                float v1 = acc[mt][ng][half * 2 + 1] + bb.y;
                if (EPI == 1) {
                    float2 rv = *(const float2*)(res + (size_t)row * N + col);
                    v0 += rv.x; v1 += rv.y;
                }
                if (EPI == 2) {
                    v0 = gelu_exact(v0);
                    v1 = gelu_exact(v1);
                    __nv_bfloat16 h0 = __float2bfloat16(v0);
                    __nv_bfloat16 h1 = __float2bfloat16(v1);
                    float l0 = v0 - __bfloat162float(h0);
                    float l1 = v1 - __bfloat162float(h1);
                    size_t rb = (size_t)row * (2 * Kout);
                    *(__nv_bfloat162*)(Cs + rb + col) =
                        __nv_bfloat162(h0, h1);
                    *(__nv_bfloat162*)(Cs + rb + Kout + col) =
                        __nv_bfloat162(__float2bfloat16(l0), __float2bfloat16(l1));
                } else {
                    *(float2*)(Cf + (size_t)row * N + col) = make_float2(v0, v1);
                }
            }
        }
    }
}

// ---------------- attention: one block per (b, h), fp32; writes split ctx ----------------
#define ATTN_SMEM ((NT * 64 + NT * 64 + NT * 65 + 8 * NT) * (int)sizeof(float))

__global__ void __launch_bounds__(256)
attn_kernel(const float* __restrict__ qkv, __nv_bfloat16* __restrict__ cs) {
    extern __shared__ float sm[];
    float* Qs = sm;
    float* Vs = Qs + NT * 64;
    float* Ks = Vs + NT * 64;
    float* sbuf = Ks + NT * 65;
    int b = blockIdx.x >> 3, h = blockIdx.x & 7;
    const float* base = qkv + (size_t)b * NT * (3 * DIM) + h * HD;
    int tid = threadIdx.x;
    for (int i = tid; i < NT * 64; i += 256) {
        int n = i >> 6, d = i & 63;
        const float* p = base + (size_t)n * (3 * DIM) + d;
        Qs[i] = p[0];
        Ks[n * 65 + d] = p[DIM];
        Vs[i] = p[2 * DIM];
    }
    __syncthreads();
    int wid = tid >> 5, lane = tid & 31;
    float* srow = sbuf + wid * NT;
    const float2* V2 = (const float2*)Vs;

    for (int row = wid; row < NT; row += 8) {
        const float* q = Qs + row * 64;
        float mx = -1e30f;
        for (int m = lane; m < NT; m += 32) {
            const float* kr = Ks + m * 65;
            float s = 0.f;
#pragma unroll
            for (int d = 0; d < 64; d++) s = fmaf(q[d], kr[d], s);
            s *= 0.125f;
            srow[m] = s;
            mx = fmaxf(mx, s);
        }
#pragma unroll
        for (int o = 16; o; o >>= 1) mx = fmaxf(mx, __shfl_xor_sync(0xffffffffu, mx, o));
        float sum = 0.f;
        for (int m = lane; m < NT; m += 32) {
            float e = __expf(srow[m] - mx);
            srow[m] = e;
            sum += e;
        }
#pragma unroll
        for (int o = 16; o; o >>= 1) sum += __shfl_xor_sync(0xffffffffu, sum, o);
        float inv = 1.f / sum;
        __syncwarp();
        float ax = 0.f, ay = 0.f;
        for (int m = 0; m < NT; m++) {
            float p = srow[m];
            float2 v = V2[m * 32 + lane];
            ax = fmaf(p, v.x, ax);
            ay = fmaf(p, v.y, ay);
        }
        size_t rb = (size_t)(b * NT + row) * (2 * DIM);
        int col = h * HD + lane * 2;
        split_store(cs, rb, DIM, col,     ax * inv);
        split_store(cs, rb, DIM, col + 1, ay * inv);
        __syncwarp();
    }
}

// ---------------- layernorm: y -> x fp32 + xs split ----------------
__global__ void __launch_bounds__(128)
ln_kernel(const float* __restrict__ in, const float* __restrict__ w,
          const float* __restrict__ bp, float* __restrict__ out,
          __nv_bfloat16* __restrict__ xs) {
    int row = blockIdx.x;
    int t = threadIdx.x;
    float4 v = ((const float4*)(in + (size_t)row * DIM))[t];
    float s  = v.x + v.y + v.z + v.w;
    float sq = v.x * v.x + v.y * v.y + v.z * v.z + v.w * v.w;
#pragma unroll
    for (int o = 16; o; o >>= 1) {
        s  += __shfl_xor_sync(0xffffffffu, s, o);
        sq += __shfl_xor_sync(0xffffffffu, sq, o);
    }
    __shared__ float ss[4], ssq[4];
    int wid = t >> 5, lane = t & 31;
    if (lane == 0) { ss[wid] = s; ssq[wid] = sq; }
    __syncthreads();
    s  = ss[0] + ss[1] + ss[2] + ss[3];
    sq = ssq[0] + ssq[1] + ssq[2] + ssq[3];
    float mean = s * (1.f / 512.f);
    float var  = sq * (1.f / 512.f) - mean * mean;
    float r = rsqrtf(var + 1e-5f);
    float4 wv = ((const float4*)w)[t];
    float4 bv = ((const float4*)bp)[t];
    float4 o;
    o.x = (v.x - mean) * r * wv.x + bv.x;
    o.y = (v.y - mean) * r * wv.y + bv.y;
    o.z = (v.z - mean) * r * wv.z + bv.z;
    o.w = (v.w - mean) * r * wv.w + bv.w;
    ((float4*)(out + (size_t)row * DIM))[t] = o;
    size_t rb = (size_t)row * (2 * DIM);
    int c0 = t * 4;
    split_store(xs, rb, DIM, c0 + 0, o.x);
    split_store(xs, rb, DIM, c0 + 1, o.y);
    split_store(xs, rb, DIM, c0 + 2, o.z);
    split_store(xs, rb, DIM, c0 + 3, o.w);
}

// ---------------- host launcher ----------------
extern "C" void kernel_launch(void* const* d_in, const int* in_sizes, int n_in,
                              void* d_out, int out_size) {
    (void)in_sizes; (void)n_in; (void)out_size;
    const float* img    = (const float*)d_in[0];
    const float* pw     = (const float*)d_in[1];
    const float* pb     = (const float*)d_in[2];
    const float* cls    = (const float*)d_in[3];
    const float* pos    = (const float*)d_in[4];
    const float* ipw    = (const float*)d_in[5];
    const float* ipb    = (const float*)d_in[6];
    const float* opw    = (const float*)d_in[7];
    const float* opb    = (const float*)d_in[8];
    const float* ln1w   = (const float*)d_in[9];
    const float* ln1b   = (const float*)d_in[10];
    const float* fc1w   = (const float*)d_in[11];
    const float* fc1b   = (const float*)d_in[12];
    const float* fc2w   = (const float*)d_in[13];
    const float* fc2b   = (const float*)d_in[14];
    const float* ln2w   = (const float*)d_in[15];
    const float* ln2b   = (const float*)d_in[16];
    float* out = (float*)d_out;

    float *x, *y, *qkv, *emb;
    __nv_bfloat16 *xps, *xs, *cs, *hs, *pws, *ipws, *opws, *fc1ws, *fc2ws;
    cudaGetSymbolAddress((void**)&x,     g_x);
    cudaGetSymbolAddress((void**)&y,     g_y);
    cudaGetSymbolAddress((void**)&qkv,   g_qkv);
    cudaGetSymbolAddress((void**)&emb,   g_emb);
    cudaGetSymbolAddress((void**)&xps,   g_xps);
    cudaGetSymbolAddress((void**)&xs,    g_xs);
    cudaGetSymbolAddress((void**)&cs,    g_cs);
    cudaGetSymbolAddress((void**)&hs,    g_hs);
    cudaGetSymbolAddress((void**)&pws,   g_pws);
    cudaGetSymbolAddress((void**)&ipws,  g_ipws);
    cudaGetSymbolAddress((void**)&opws,  g_opws);
    cudaGetSymbolAddress((void**)&fc1ws, g_fc1ws);
    cudaGetSymbolAddress((void**)&fc2ws, g_fc2ws);

    cudaFuncSetAttribute(attn_kernel, cudaFuncAttributeMaxDynamicSharedMemorySize, ATTN_SMEM);
    cudaFuncSetAttribute(mma_gemm_kernel<0>, cudaFuncAttributeMaxDynamicSharedMemorySize, GEMM_SMEM_BYTES);
    cudaFuncSetAttribute(mma_gemm_kernel<1>, cudaFuncAttributeMaxDynamicSharedMemorySize, GEMM_SMEM_BYTES);
    cudaFuncSetAttribute(mma_gemm_kernel<2>, cudaFuncAttributeMaxDynamicSharedMemorySize, GEMM_SMEM_BYTES);

    // ---- weight splits ----
    {
        int t;
        t = DIM * CPP;
        wsplit_kernel<<<(t + 255) / 256, 256>>>(pw, pws, CPP, t);
        t = 6 * 3 * DIM * DIM;
        wsplit_kernel<<<(t + 255) / 256, 256>>>(ipw, ipws, DIM, t);
        t = 6 * DIM * DIM;
        wsplit_kernel<<<(t + 255) / 256, 256>>>(opw, opws, DIM, t);
        t = 6 * MLPD * DIM;
        wsplit_kernel<<<(t + 255) / 256, 256>>>(fc1w, fc1ws, DIM, t);
        t = 6 * DIM * MLPD;
        wsplit_kernel<<<(t + 255) / 256, 256>>>(fc2w, fc2ws, MLPD, t);
    }

    // ---- patch embed ----
    {
        int n = T_PAT * CPP;
        patchify_kernel<<<(n + 255) / 256, 256>>>(img, xps);
        mma_gemm_kernel<0><<<dim3(DIM / 128, MP2 / 128), 256, GEMM_SMEM_BYTES>>>(
            xps, pws, pb, nullptr, emb, nullptr, CPP, DIM, 0);
        int m = T_TOK * DIM;
        assemble_kernel<<<(m + 255) / 256, 256>>>(emb, cls, pos, x, xs);
    }

    for (int i = 0; i < 6; i++) {
        const __nv_bfloat16* ipws_i  = ipws  + (size_t)i * 3 * DIM * 2 * DIM;
        const __nv_bfloat16* opws_i  = opws  + (size_t)i * DIM * 2 * DIM;
        const __nv_bfloat16* fc1ws_i = fc1ws + (size_t)i * MLPD * 2 * DIM;
        const __nv_bfloat16* fc2ws_i = fc2ws + (size_t)i * DIM * 2 * MLPD;
        const float* ipb_i  = ipb  + (size_t)i * 3 * DIM;
        const float* opb_i  = opb  + (size_t)i * DIM;
        const float* fc1b_i = fc1b + (size_t)i * MLPD;
        const float* fc2b_i = fc2b + (size_t)i * DIM;

        mma_gemm_kernel<0><<<dim3(3 * DIM / 128, MP2 / 128), 256, GEMM_SMEM_BYTES>>>(
            xs, ipws_i, ipb_i, nullptr, qkv, nullptr, DIM, 3 * DIM, 0);
        attn_kernel<<<B_ * HEADS, 256, ATTN_SMEM>>>(qkv, cs);
        mma_gemm_kernel<1><<<dim3(DIM / 128, MP2 / 128), 256, GEMM_SMEM_BYTES>>>(
            cs, opws_i, opb_i, x, y, nullptr, DIM, DIM, 0);
        ln_kernel<<<T_TOK, 128>>>(y, ln1w + i * DIM, ln1b + i * DIM, x, xs);
        mma_gemm_kernel<2><<<dim3(MLPD / 128, MP2 / 128), 256, GEMM_SMEM_BYTES>>>(
            xs, fc1ws_i, fc1b_i, nullptr, nullptr, hs, DIM, MLPD, MLPD);
        mma_gemm_kernel<1><<<dim3(DIM / 128, MP2 / 128), 256, GEMM_SMEM_BYTES>>>(
            hs, fc2ws_i, fc2b_i, x, y, nullptr, MLPD, DIM, 0);
        ln_kernel<<<T_TOK, 128>>>(y, ln2w + i * DIM, ln2b + i * DIM, x, xs);
    }

    {
        int n = B_ * DIM;
        clsout_kernel<<<(n + 255) / 256, 256>>>(x, out);
    }
}

// round 5
// speedup vs baseline: 2.0209x; 1.1613x over previous
#include <cuda_runtime.h>
#include <cuda_bf16.h>
#include <cuda.h>
#include <math.h>
#include <stdint.h>

// ---------------- model constants ----------------
#define B_     64
#define NPATCH 196
#define NT     197
#define DIM    512
#define HEADS  8
#define HD     64
#define MLPD   2048
#define CPP    768
#define T_TOK  (B_*NT)      // 12608
#define T_PAT  (B_*NPATCH)  // 12544
#define MP2    12800        // padded rows: 128*100

// ---------------- helpers ----------------
__device__ __forceinline__ uint32_t smem_to_u32(const void* p) {
    uint32_t a;
    asm("{ .reg .u64 t; cvta.to.shared.u64 t, %1; cvt.u32.u64 %0, t; }" : "=r"(a) : "l"(p));
    return a;
}
#define SWZ128(o) ((o) ^ (((o) >> 3) & 0x70))

__device__ __forceinline__ void cp16(uint32_t dst, const void* src) {
    asm volatile("cp.async.cg.shared.global [%0], [%1], 16;" :: "r"(dst), "l"(src));
}
#define CP_COMMIT() asm volatile("cp.async.commit_group;" ::: "memory")
#define CP_WAIT(n)  asm volatile("cp.async.wait_group %0;" :: "n"(n) : "memory")

#define LDMATRIX_X4(r, addr) \
    asm volatile("ldmatrix.sync.aligned.m8n8.x4.shared.b16 {%0,%1,%2,%3}, [%4];" \
        : "=r"((r)[0]), "=r"((r)[1]), "=r"((r)[2]), "=r"((r)[3]) : "r"(addr))

__device__ __forceinline__ void mma_bf16(float* c, const uint32_t* a, uint32_t b0, uint32_t b1) {
    asm volatile(
        "mma.sync.aligned.m16n8k16.row.col.f32.bf16.bf16.f32 "
        "{%0,%1,%2,%3}, {%4,%5,%6,%7}, {%8,%9}, {%0,%1,%2,%3};"
        : "+f"(c[0]), "+f"(c[1]), "+f"(c[2]), "+f"(c[3])
        : "r"(a[0]), "r"(a[1]), "r"(a[2]), "r"(a[3]), "r"(b0), "r"(b1));
}

// ---------------- scratch (device globals: zero-init, allocation-free) ----------------
__device__ float g_x   [MP2 * DIM];
__device__ float g_y   [MP2 * DIM];
__device__ float g_qkv [MP2 * 3 * DIM];
__device__ float g_emb [MP2 * DIM];
__device__ __align__(16) __nv_bfloat16 g_xps  [MP2 * 2 * CPP];
__device__ __align__(16) __nv_bfloat16 g_xs   [MP2 * 2 * DIM];
__device__ __align__(16) __nv_bfloat16 g_cs   [MP2 * 2 * DIM];
__device__ __align__(16) __nv_bfloat16 g_hs   [MP2 * 2 * MLPD];
__device__ __align__(16) __nv_bfloat16 g_pws  [DIM * 2 * CPP];
__device__ __align__(16) __nv_bfloat16 g_ipws [6 * 3 * DIM * 2 * DIM];
__device__ __align__(16) __nv_bfloat16 g_opws [6 * DIM * 2 * DIM];
__device__ __align__(16) __nv_bfloat16 g_fc1ws[6 * MLPD * 2 * DIM];
__device__ __align__(16) __nv_bfloat16 g_fc2ws[6 * DIM * 2 * MLPD];

__device__ __forceinline__ void split_store(__nv_bfloat16* dst, size_t rb, int K, int c, float v) {
    __nv_bfloat16 hi = __float2bfloat16(v);
    float lo = v - __bfloat162float(hi);
    dst[rb + c]     = hi;
    dst[rb + K + c] = __float2bfloat16(lo);
}

// ---------------- all weight splits in one launch ----------------
#define WS1 (DIM * CPP)                    // pw
#define WS2 (6 * 3 * DIM * DIM)            // ipw
#define WS3 (6 * DIM * DIM)                // opw
#define WS4 (6 * MLPD * DIM)               // fc1w
#define WS5 (6 * DIM * MLPD)               // fc2w
#define WS_TOTAL (WS1 + WS2 + WS3 + WS4 + WS5)

__global__ void wsplit_all_kernel(const float* __restrict__ pw, const float* __restrict__ ipw,
                                  const float* __restrict__ opw, const float* __restrict__ fc1w,
                                  const float* __restrict__ fc2w,
                                  __nv_bfloat16* __restrict__ pws, __nv_bfloat16* __restrict__ ipws,
                                  __nv_bfloat16* __restrict__ opws, __nv_bfloat16* __restrict__ fc1ws,
                                  __nv_bfloat16* __restrict__ fc2ws) {
    int idx = blockIdx.x * blockDim.x + threadIdx.x;
    if (idx >= WS_TOTAL) return;
    const float* src; __nv_bfloat16* dst; int K;
    if (idx < WS1)                         { src = pw;   dst = pws;   K = CPP;  }
    else if ((idx -= WS1) < WS2)           { src = ipw;  dst = ipws;  K = DIM;  }
    else if ((idx -= WS2) < WS3)           { src = opw;  dst = opws;  K = DIM;  }
    else if ((idx -= WS3) < WS4)           { src = fc1w; dst = fc1ws; K = DIM;  }
    else { idx -= WS4;                       src = fc2w; dst = fc2ws; K = MLPD; }
    int n = idx / K, c = idx % K;
    split_store(dst, (size_t)n * 2 * K, K, c, src[idx]);
}

__global__ void patchify_kernel(const float* __restrict__ img, __nv_bfloat16* __restrict__ xps) {
    int idx = blockIdx.x * blockDim.x + threadIdx.x;
    if (idx >= T_PAT * CPP) return;
    int f   = idx % CPP;
    int row = idx / CPP;
    int b = row / NPATCH, p = row % NPATCH;
    int gh = p / 14, gw = p % 14;
    int c  = f % 3;
    int pp = f / 3;
    int p1 = pp >> 4, p2 = pp & 15;
    float v = img[(((size_t)(b * 3 + c)) * 224 + gh * 16 + p1) * 224 + gw * 16 + p2];
    split_store(xps, (size_t)row * (2 * CPP), CPP, f, v);
}

__global__ void assemble_kernel(const float* __restrict__ emb,
                                const float* __restrict__ cls,
                                const float* __restrict__ pos,
                                float* __restrict__ x, __nv_bfloat16* __restrict__ xs) {
    int idx = blockIdx.x * blockDim.x + threadIdx.x;
    if (idx >= T_TOK * DIM) return;
    int d = idx & (DIM - 1);
    int t = idx >> 9;
    int b = t / NT, n = t % NT;
    float v = (n == 0) ? cls[d] : emb[((size_t)(b * NPATCH + n - 1)) * DIM + d];
    v += pos[n * DIM + d];
    x[idx] = v;
    split_store(xs, (size_t)t * (2 * DIM), DIM, d, v);
}

__global__ void clsout_kernel(const float* __restrict__ x, float* __restrict__ out) {
    int idx = blockIdx.x * blockDim.x + threadIdx.x;
    if (idx >= B_ * DIM) return;
    int b = idx >> 9, d = idx & (DIM - 1);
    out[idx] = x[((size_t)b * NT) * DIM + d];
}

__device__ __forceinline__ float gelu_exact(float v) {
    return 0.5f * v * (1.0f + erff(v * 0.70710678118654752f));
}

// =====================================================================
// HMMA GEMM: C[M,N] = A[M,K](split hi|lo) @ W[N,K](split)^T, 3-term bf16.
// CTA 128x128, BK=64 chunks, 3-stage cp.async ring (one sync per chunk),
// 2 CTAs/SM. 8 warps: 4(m) x 2(n), warp tile m32 x n64, mma.m16n8k16.
// EPI 0: fp32 bias   1: fp32 bias+res   2: split-bf16 gelu(bias+acc)
// =====================================================================
#define GEMM_SMEM_BYTES 98304   // 3 stages x (16KB A + 16KB B)

__device__ __forceinline__ void prefetch_tile(const __nv_bfloat16* __restrict__ G,
                                              int K2, uint32_t sbase, int tid) {
#pragma unroll
    for (int r = 0; r < 4; r++) {
        int i = tid + r * 256;
        int row = i >> 3, seg = i & 7;
        cp16(sbase + SWZ128(row * 128 + seg * 16), G + (size_t)row * K2 + seg * 8);
    }
}

template <int EPI>
__global__ void __launch_bounds__(256, 2)
mma_gemm_kernel(const __nv_bfloat16* __restrict__ A, const __nv_bfloat16* __restrict__ W,
                const float* __restrict__ bias, const float* __restrict__ res,
                float* __restrict__ Cf, __nv_bfloat16* __restrict__ Cs,
                int K, int N, int Kout) {
    extern __shared__ char smc[];
    const uint32_t sb = smem_to_u32(smc);
    const int tid = threadIdx.x, wid = tid >> 5, lane = tid & 31;
    const int bm = blockIdx.y * 128, bn = blockIdx.x * 128;
    const int K2 = 2 * K;
    const int NCk = K >> 6;
    const int NC = 3 * NCk;
    const int mbase = (wid >> 1) * 32;
    const int nbase = (wid & 1) * 64;

    float acc[2][8][4];
#pragma unroll
    for (int mt = 0; mt < 2; mt++)
#pragma unroll
        for (int ng = 0; ng < 8; ng++)
#pragma unroll
            for (int r = 0; r < 4; r++) acc[mt][ng][r] = 0.f;

    const __nv_bfloat16* Abase = A + (size_t)bm * K2;
    const __nv_bfloat16* Bbase = W + (size_t)bn * K2;

    // prologue: stages 0,1
    prefetch_tile(Abase, K2, sb, tid);
    prefetch_tile(Bbase, K2, sb + 16384, tid);
    CP_COMMIT();
    {
        int ca = 1 < 2 * NCk ? 1 : 1 - 2 * NCk;
        int cb = 1 < NCk ? 1 : 1 - NCk;
        prefetch_tile(Abase + ca * 64, K2, sb + 32768, tid);
        prefetch_tile(Bbase + cb * 64, K2, sb + 49152, tid);
        CP_COMMIT();
    }

    const int lrow8 = (lane & 7) + ((lane >> 3) & 1) * 8;
    const int lkoff = (lane >> 4) * 16;

    int sbuf = 0;   // stage of chunk c (0,1,2 rotating)
    for (int c = 0; c < NC; c++) {
        if (c + 1 < NC) { CP_WAIT(1); } else { CP_WAIT(0); }
        __syncthreads();

        // prefetch chunk c+2 into the stage freed at iter c-1
        if (c + 2 < NC) {
            int cn = c + 2;
            int ca = (cn < 2 * NCk) ? cn : (cn - 2 * NCk);
            int cb = (cn < NCk) ? cn : (cn - NCk);
            int ps = sbuf + 2; if (ps >= 3) ps -= 3;
            prefetch_tile(Abase + ca * 64, K2, sb + ps * 32768, tid);
            prefetch_tile(Bbase + cb * 64, K2, sb + ps * 32768 + 16384, tid);
            CP_COMMIT();
        } else {
            CP_COMMIT();   // keep group counting uniform
        }

        const uint32_t sA = sb + sbuf * 32768;
        const uint32_t sB = sA + 16384;
#pragma unroll
        for (int s = 0; s < 4; s++) {
            uint32_t af[2][4], bf[4][4];
#pragma unroll
            for (int mt = 0; mt < 2; mt++) {
                int row = mbase + mt * 16 + lrow8;
                LDMATRIX_X4(af[mt], sA + SWZ128(row * 128 + s * 32 + lkoff));
            }
#pragma unroll
            for (int ng2 = 0; ng2 < 4; ng2++) {
                int row = nbase + ng2 * 16 + lrow8;
                LDMATRIX_X4(bf[ng2], sB + SWZ128(row * 128 + s * 32 + lkoff));
            }
#pragma unroll
            for (int mt = 0; mt < 2; mt++)
#pragma unroll
                for (int ng2 = 0; ng2 < 4; ng2++) {
                    mma_bf16(acc[mt][ng2 * 2],     af[mt], bf[ng2][0], bf[ng2][2]);
                    mma_bf16(acc[mt][ng2 * 2 + 1], af[mt], bf[ng2][1], bf[ng2][3]);
                }
        }
        sbuf++; if (sbuf == 3) sbuf = 0;
    }

    // ---- epilogue: direct fragment stores ----
    const int qr = lane >> 2;
    const int qc = (lane & 3) * 2;
#pragma unroll
    for (int mt = 0; mt < 2; mt++) {
#pragma unroll
        for (int ng = 0; ng < 8; ng++) {
            const int col = bn + nbase + ng * 8 + qc;
            const float2 bb = *(const float2*)(bias + col);
#pragma unroll
            for (int half = 0; half < 2; half++) {
                const int row = bm + mbase + mt * 16 + qr + half * 8;
                float v0 = acc[mt][ng][half * 2 + 0] + bb.x;
                float v1 = acc[mt][ng][half * 2 + 1] + bb.y;
                if (EPI == 1) {
                    float2 rv = *(const float2*)(res + (size_t)row * N + col);
                    v0 += rv.x; v1 += rv.y;
                }
                if (EPI == 2) {
                    v0 = gelu_exact(v0);
                    v1 = gelu_exact(v1);
                    __nv_bfloat16 h0 = __float2bfloat16(v0);
                    __nv_bfloat16 h1 = __float2bfloat16(v1);
                    float l0 = v0 - __bfloat162float(h0);
                    float l1 = v1 - __bfloat162float(h1);
                    size_t rb = (size_t)row * (2 * Kout);
                    *(__nv_bfloat162*)(Cs + rb + col) = __nv_bfloat162(h0, h1);
                    *(__nv_bfloat162*)(Cs + rb + Kout + col) =
                        __nv_bfloat162(__float2bfloat16(l0), __float2bfloat16(l1));
                } else {
                    *(float2*)(Cf + (size_t)row * N + col) = make_float2(v0, v1);
                }
            }
        }
    }
}

// ---------------- attention: one block per (b, h), fp32; writes split ctx ----------------
#define ATTN_SMEM ((NT * 64 + NT * 64 + NT * 65 + 8 * NT) * (int)sizeof(float))

__global__ void __launch_bounds__(256)
attn_kernel(const float* __restrict__ qkv, __nv_bfloat16* __restrict__ cs) {
    extern __shared__ float sm[];
    float* Qs = sm;
    float* Vs = Qs + NT * 64;
    float* Ks = Vs + NT * 64;
    float* sbuf = Ks + NT * 65;
    int b = blockIdx.x >> 3, h = blockIdx.x & 7;
    const float* base = qkv + (size_t)b * NT * (3 * DIM) + h * HD;
    int tid = threadIdx.x;
    for (int i = tid; i < NT * 64; i += 256) {
        int n = i >> 6, d = i & 63;
        const float* p = base + (size_t)n * (3 * DIM) + d;
        Qs[i] = p[0];
        Ks[n * 65 + d] = p[DIM];
        Vs[i] = p[2 * DIM];
    }
    __syncthreads();
    int wid = tid >> 5, lane = tid & 31;
    float* srow = sbuf + wid * NT;
    const float2* V2 = (const float2*)Vs;

    for (int row = wid; row < NT; row += 8) {
        const float* q = Qs + row * 64;
        float mx = -1e30f;
        for (int m = lane; m < NT; m += 32) {
            const float* kr = Ks + m * 65;
            float s = 0.f;
#pragma unroll
            for (int d = 0; d < 64; d++) s = fmaf(q[d], kr[d], s);
            s *= 0.125f;
            srow[m] = s;
            mx = fmaxf(mx, s);
        }
#pragma unroll
        for (int o = 16; o; o >>= 1) mx = fmaxf(mx, __shfl_xor_sync(0xffffffffu, mx, o));
        float sum = 0.f;
        for (int m = lane; m < NT; m += 32) {
            float e = __expf(srow[m] - mx);
            srow[m] = e;
            sum += e;
        }
#pragma unroll
        for (int o = 16; o; o >>= 1) sum += __shfl_xor_sync(0xffffffffu, sum, o);
        float inv = 1.f / sum;
        __syncwarp();
        float ax = 0.f, ay = 0.f;
        for (int m = 0; m < NT; m++) {
            float p = srow[m];
            float2 v = V2[m * 32 + lane];
            ax = fmaf(p, v.x, ax);
            ay = fmaf(p, v.y, ay);
        }
        size_t rb = (size_t)(b * NT + row) * (2 * DIM);
        int col = h * HD + lane * 2;
        split_store(cs, rb, DIM, col,     ax * inv);
        split_store(cs, rb, DIM, col + 1, ay * inv);
        __syncwarp();
    }
}

// ---------------- layernorm: y -> x fp32 + xs split ----------------
__global__ void __launch_bounds__(128)
ln_kernel(const float* __restrict__ in, const float* __restrict__ w,
          const float* __restrict__ bp, float* __restrict__ out,
          __nv_bfloat16* __restrict__ xs) {
    int row = blockIdx.x;
    int t = threadIdx.x;
    float4 v = ((const float4*)(in + (size_t)row * DIM))[t];
    float s  = v.x + v.y + v.z + v.w;
    float sq = v.x * v.x + v.y * v.y + v.z * v.z + v.w * v.w;
#pragma unroll
    for (int o = 16; o; o >>= 1) {
        s  += __shfl_xor_sync(0xffffffffu, s, o);
        sq += __shfl_xor_sync(0xffffffffu, sq, o);
    }
    __shared__ float ss[4], ssq[4];
    int wid = t >> 5, lane = t & 31;
    if (lane == 0) { ss[wid] = s; ssq[wid] = sq; }
    __syncthreads();
    s  = ss[0] + ss[1] + ss[2] + ss[3];
    sq = ssq[0] + ssq[1] + ssq[2] + ssq[3];
    float mean = s * (1.f / 512.f);
    float var  = sq * (1.f / 512.f) - mean * mean;
    float r = rsqrtf(var + 1e-5f);
    float4 wv = ((const float4*)w)[t];
    float4 bv = ((const float4*)bp)[t];
    float4 o;
    o.x = (v.x - mean) * r * wv.x + bv.x;
    o.y = (v.y - mean) * r * wv.y + bv.y;
    o.z = (v.z - mean) * r * wv.z + bv.z;
    o.w = (v.w - mean) * r * wv.w + bv.w;
    ((float4*)(out + (size_t)row * DIM))[t] = o;
    size_t rb = (size_t)row * (2 * DIM);
    int c0 = t * 4;
    split_store(xs, rb, DIM, c0 + 0, o.x);
    split_store(xs, rb, DIM, c0 + 1, o.y);
    split_store(xs, rb, DIM, c0 + 2, o.z);
    split_store(xs, rb, DIM, c0 + 3, o.w);
}

// ---------------- host launcher ----------------
extern "C" void kernel_launch(void* const* d_in, const int* in_sizes, int n_in,
                              void* d_out, int out_size) {
    (void)in_sizes; (void)n_in; (void)out_size;
    const float* img    = (const float*)d_in[0];
    const float* pw     = (const float*)d_in[1];
    const float* pb     = (const float*)d_in[2];
    const float* cls    = (const float*)d_in[3];
    const float* pos    = (const float*)d_in[4];
    const float* ipw    = (const float*)d_in[5];
    const float* ipb    = (const float*)d_in[6];
    const float* opw    = (const float*)d_in[7];
    const float* opb    = (const float*)d_in[8];
    const float* ln1w   = (const float*)d_in[9];
    const float* ln1b   = (const float*)d_in[10];
    const float* fc1w   = (const float*)d_in[11];
    const float* fc1b   = (const float*)d_in[12];
    const float* fc2w   = (const float*)d_in[13];
    const float* fc2b   = (const float*)d_in[14];
    const float* ln2w   = (const float*)d_in[15];
    const float* ln2b   = (const float*)d_in[16];
    float* out = (float*)d_out;

    float *x, *y, *qkv, *emb;
    __nv_bfloat16 *xps, *xs, *cs, *hs, *pws, *ipws, *opws, *fc1ws, *fc2ws;
    cudaGetSymbolAddress((void**)&x,     g_x);
    cudaGetSymbolAddress((void**)&y,     g_y);
    cudaGetSymbolAddress((void**)&qkv,   g_qkv);
    cudaGetSymbolAddress((void**)&emb,   g_emb);
    cudaGetSymbolAddress((void**)&xps,   g_xps);
    cudaGetSymbolAddress((void**)&xs,    g_xs);
    cudaGetSymbolAddress((void**)&cs,    g_cs);
    cudaGetSymbolAddress((void**)&hs,    g_hs);
    cudaGetSymbolAddress((void**)&pws,   g_pws);
    cudaGetSymbolAddress((void**)&ipws,  g_ipws);
    cudaGetSymbolAddress((void**)&opws,  g_opws);
    cudaGetSymbolAddress((void**)&fc1ws, g_fc1ws);
    cudaGetSymbolAddress((void**)&fc2ws, g_fc2ws);

    cudaFuncSetAttribute(attn_kernel, cudaFuncAttributeMaxDynamicSharedMemorySize, ATTN_SMEM);
    cudaFuncSetAttribute(mma_gemm_kernel<0>, cudaFuncAttributeMaxDynamicSharedMemorySize, GEMM_SMEM_BYTES);
    cudaFuncSetAttribute(mma_gemm_kernel<1>, cudaFuncAttributeMaxDynamicSharedMemorySize, GEMM_SMEM_BYTES);
    cudaFuncSetAttribute(mma_gemm_kernel<2>, cudaFuncAttributeMaxDynamicSharedMemorySize, GEMM_SMEM_BYTES);

    // ---- all weight splits (1 launch) ----
    wsplit_all_kernel<<<(WS_TOTAL + 255) / 256, 256>>>(pw, ipw, opw, fc1w, fc2w,
                                                       pws, ipws, opws, fc1ws, fc2ws);

    // ---- patch embed ----
    {
        int n = T_PAT * CPP;
        patchify_kernel<<<(n + 255) / 256, 256>>>(img, xps);
        mma_gemm_kernel<0><<<dim3(DIM / 128, MP2 / 128), 256, GEMM_SMEM_BYTES>>>(
            xps, pws, pb, nullptr, emb, nullptr, CPP, DIM, 0);
        int m = T_TOK * DIM;
        assemble_kernel<<<(m + 255) / 256, 256>>>(emb, cls, pos, x, xs);
    }

    for (int i = 0; i < 6; i++) {
        const __nv_bfloat16* ipws_i  = ipws  + (size_t)i * 3 * DIM * 2 * DIM;
        const __nv_bfloat16* opws_i  = opws  + (size_t)i * DIM * 2 * DIM;
        const __nv_bfloat16* fc1ws_i = fc1ws + (size_t)i * MLPD * 2 * DIM;
        const __nv_bfloat16* fc2ws_i = fc2ws + (size_t)i * DIM * 2 * MLPD;
        const float* ipb_i  = ipb  + (size_t)i * 3 * DIM;
        const float* opb_i  = opb  + (size_t)i * DIM;
        const float* fc1b_i = fc1b + (size_t)i * MLPD;
        const float* fc2b_i = fc2b + (size_t)i * DIM;

        mma_gemm_kernel<0><<<dim3(3 * DIM / 128, MP2 / 128), 256, GEMM_SMEM_BYTES>>>(
            xs, ipws_i, ipb_i, nullptr, qkv, nullptr, DIM, 3 * DIM, 0);
        attn_kernel<<<B_ * HEADS, 256, ATTN_SMEM>>>(qkv, cs);
        mma_gemm_kernel<1><<<dim3(DIM / 128, MP2 / 128), 256, GEMM_SMEM_BYTES>>>(
            cs, opws_i, opb_i, x, y, nullptr, DIM, DIM, 0);
        ln_kernel<<<T_TOK, 128>>>(y, ln1w + i * DIM, ln1b + i * DIM, x, xs);
        mma_gemm_kernel<2><<<dim3(MLPD / 128, MP2 / 128), 256, GEMM_SMEM_BYTES>>>(
            xs, fc1ws_i, fc1b_i, nullptr, nullptr, hs, DIM, MLPD, MLPD);
        mma_gemm_kernel<1><<<dim3(DIM / 128, MP2 / 128), 256, GEMM_SMEM_BYTES>>>(
            hs, fc2ws_i, fc2b_i, x, y, nullptr, MLPD, DIM, 0);
        ln_kernel<<<T_TOK, 128>>>(y, ln2w + i * DIM, ln2b + i * DIM, x, xs);
    }

    {
        int n = B_ * DIM;
        clsout_kernel<<<(n + 255) / 256, 256>>>(x, out);
    }
}

// round 6
// speedup vs baseline: 2.2242x; 1.1006x over previous
#include <cuda_runtime.h>
#include <cuda_bf16.h>
#include <cuda.h>
#include <math.h>
#include <stdint.h>

// ---------------- model constants ----------------
#define B_     64
#define NPATCH 196
#define NT     197
#define DIM    512
#define HEADS  8
#define HD     64
#define MLPD   2048
#define CPP    768
#define T_TOK  (B_*NT)      // 12608
#define T_PAT  (B_*NPATCH)  // 12544
#define MP2    12800        // padded rows: 128*100

// ---------------- helpers ----------------
__device__ __forceinline__ uint32_t smem_to_u32(const void* p) {
    uint32_t a;
    asm("{ .reg .u64 t; cvta.to.shared.u64 t, %1; cvt.u32.u64 %0, t; }" : "=r"(a) : "l"(p));
    return a;
}
#define SWZ128(o) ((o) ^ (((o) >> 3) & 0x70))

__device__ __forceinline__ void cp16(uint32_t dst, const void* src) {
    asm volatile("cp.async.cg.shared.global [%0], [%1], 16;" :: "r"(dst), "l"(src));
}
#define CP_COMMIT() asm volatile("cp.async.commit_group;" ::: "memory")
#define CP_WAIT(n)  asm volatile("cp.async.wait_group %0;" :: "n"(n) : "memory")

#define LDMATRIX_X4(r, addr) \
    asm volatile("ldmatrix.sync.aligned.m8n8.x4.shared.b16 {%0,%1,%2,%3}, [%4];" \
        : "=r"((r)[0]), "=r"((r)[1]), "=r"((r)[2]), "=r"((r)[3]) : "r"(addr))

__device__ __forceinline__ void mma_bf16(float* c, const uint32_t* a, uint32_t b0, uint32_t b1) {
    asm volatile(
        "mma.sync.aligned.m16n8k16.row.col.f32.bf16.bf16.f32 "
        "{%0,%1,%2,%3}, {%4,%5,%6,%7}, {%8,%9}, {%0,%1,%2,%3};"
        : "+f"(c[0]), "+f"(c[1]), "+f"(c[2]), "+f"(c[3])
        : "r"(a[0]), "r"(a[1]), "r"(a[2]), "r"(a[3]), "r"(b0), "r"(b1));
}

// ---------------- scratch (device globals: zero-init, allocation-free) ----------------
__device__ float g_x   [MP2 * DIM];
__device__ float g_y   [MP2 * DIM];
__device__ float g_qkv [MP2 * 3 * DIM];
__device__ float g_emb [MP2 * DIM];
__device__ __align__(16) __nv_bfloat16 g_xps  [MP2 * 2 * CPP];
__device__ __align__(16) __nv_bfloat16 g_xs   [MP2 * 2 * DIM];
__device__ __align__(16) __nv_bfloat16 g_cs   [MP2 * 2 * DIM];
__device__ __align__(16) __nv_bfloat16 g_hs   [MP2 * 2 * MLPD];
__device__ __align__(16) __nv_bfloat16 g_pws  [DIM * 2 * CPP];
__device__ __align__(16) __nv_bfloat16 g_ipws [6 * 3 * DIM * 2 * DIM];
__device__ __align__(16) __nv_bfloat16 g_opws [6 * DIM * 2 * DIM];
__device__ __align__(16) __nv_bfloat16 g_fc1ws[6 * MLPD * 2 * DIM];
__device__ __align__(16) __nv_bfloat16 g_fc2ws[6 * DIM * 2 * MLPD];
// ---- CLS-path buffers (rows 64..127 stay zero forever unless noted) ----
__device__ __align__(16) __nv_bfloat16 g_cqs [128 * 2 * DIM];   // gathered CLS xs (split)
__device__ float g_qc  [128 * DIM];                             // Q of CLS rows
__device__ float g_xc  [128 * DIM];                             // gathered CLS x (residual)
__device__ __align__(16) __nv_bfloat16 g_csc [128 * 2 * DIM];   // CLS attention ctx (split)
__device__ float g_yc  [128 * DIM];
__device__ float g_xcf [128 * DIM];
__device__ __align__(16) __nv_bfloat16 g_xsc [128 * 2 * DIM];
__device__ __align__(16) __nv_bfloat16 g_hsc [128 * 2 * MLPD];

__device__ __forceinline__ void split_store(__nv_bfloat16* dst, size_t rb, int K, int c, float v) {
    __nv_bfloat16 hi = __float2bfloat16(v);
    float lo = v - __bfloat162float(hi);
    dst[rb + c]     = hi;
    dst[rb + K + c] = __float2bfloat16(lo);
}

// ---------------- all weight splits in one launch ----------------
#define WS1 (DIM * CPP)
#define WS2 (6 * 3 * DIM * DIM)
#define WS3 (6 * DIM * DIM)
#define WS4 (6 * MLPD * DIM)
#define WS5 (6 * DIM * MLPD)
#define WS_TOTAL (WS1 + WS2 + WS3 + WS4 + WS5)

__global__ void wsplit_all_kernel(const float* __restrict__ pw, const float* __restrict__ ipw,
                                  const float* __restrict__ opw, const float* __restrict__ fc1w,
                                  const float* __restrict__ fc2w,
                                  __nv_bfloat16* __restrict__ pws, __nv_bfloat16* __restrict__ ipws,
                                  __nv_bfloat16* __restrict__ opws, __nv_bfloat16* __restrict__ fc1ws,
                                  __nv_bfloat16* __restrict__ fc2ws) {
    int idx = blockIdx.x * blockDim.x + threadIdx.x;
    if (idx >= WS_TOTAL) return;
    const float* src; __nv_bfloat16* dst; int K;
    if (idx < WS1)               { src = pw;   dst = pws;   K = CPP;  }
    else if ((idx -= WS1) < WS2) { src = ipw;  dst = ipws;  K = DIM;  }
    else if ((idx -= WS2) < WS3) { src = opw;  dst = opws;  K = DIM;  }
    else if ((idx -= WS3) < WS4) { src = fc1w; dst = fc1ws; K = DIM;  }
    else { idx -= WS4;             src = fc2w; dst = fc2ws; K = MLPD; }
    int n = idx / K, c = idx % K;
    split_store(dst, (size_t)n * 2 * K, K, c, src[idx]);
}

__global__ void patchify_kernel(const float* __restrict__ img, __nv_bfloat16* __restrict__ xps) {
    int idx = blockIdx.x * blockDim.x + threadIdx.x;
    if (idx >= T_PAT * CPP) return;
    int f   = idx % CPP;
    int row = idx / CPP;
    int b = row / NPATCH, p = row % NPATCH;
    int gh = p / 14, gw = p % 14;
    int c  = f % 3;
    int pp = f / 3;
    int p1 = pp >> 4, p2 = pp & 15;
    float v = img[(((size_t)(b * 3 + c)) * 224 + gh * 16 + p1) * 224 + gw * 16 + p2];
    split_store(xps, (size_t)row * (2 * CPP), CPP, f, v);
}

__global__ void assemble_kernel(const float* __restrict__ emb,
                                const float* __restrict__ cls,
                                const float* __restrict__ pos,
                                float* __restrict__ x, __nv_bfloat16* __restrict__ xs) {
    int idx = blockIdx.x * blockDim.x + threadIdx.x;
    if (idx >= T_TOK * DIM) return;
    int d = idx & (DIM - 1);
    int t = idx >> 9;
    int b = t / NT, n = t % NT;
    float v = (n == 0) ? cls[d] : emb[((size_t)(b * NPATCH + n - 1)) * DIM + d];
    v += pos[n * DIM + d];
    x[idx] = v;
    split_store(xs, (size_t)t * (2 * DIM), DIM, d, v);
}

// gather CLS rows (token 0 of each image): fp32 x and split xs
__global__ void gather_cls_kernel(const float* __restrict__ x, const __nv_bfloat16* __restrict__ xs,
                                  float* __restrict__ xc, __nv_bfloat16* __restrict__ cqs) {
    int idx = blockIdx.x * blockDim.x + threadIdx.x;
    if (idx >= B_ * DIM) return;
    int b = idx >> 9, d = idx & (DIM - 1);
    size_t srow = (size_t)b * NT;
    xc[idx] = x[srow * DIM + d];
    cqs[(size_t)b * 2 * DIM + d]       = xs[srow * 2 * DIM + d];
    cqs[(size_t)b * 2 * DIM + DIM + d] = xs[srow * 2 * DIM + DIM + d];
}

__device__ __forceinline__ float gelu_exact(float v) {
    return 0.5f * v * (1.0f + erff(v * 0.70710678118654752f));
}

// =====================================================================
// HMMA GEMM: C[M,N] = A[M,K](split hi|lo) @ W[N,K](split)^T, 3-term bf16.
// CTA 128x128, 128 threads, 4 warps (2m x 2n) of m64 x n64.
// BK=64 chunks, 3-stage cp.async ring, one sync per chunk, 2 CTAs/SM.
// EPI 0: fp32 bias   1: fp32 bias+res   2: split-bf16 gelu(bias+acc)
// =====================================================================
#define GEMM_SMEM_BYTES 98304   // 3 stages x (16KB A + 16KB B)

__device__ __forceinline__ void prefetch_tile(const __nv_bfloat16* __restrict__ G,
                                              int K2, uint32_t sbase, int tid) {
#pragma unroll
    for (int r = 0; r < 8; r++) {
        int i = tid + r * 128;
        int row = i >> 3, seg = i & 7;
        cp16(sbase + SWZ128(row * 128 + seg * 16), G + (size_t)row * K2 + seg * 8);
    }
}

template <int EPI>
__global__ void __launch_bounds__(128, 2)
mma_gemm_kernel(const __nv_bfloat16* __restrict__ A, const __nv_bfloat16* __restrict__ W,
                const float* __restrict__ bias, const float* __restrict__ res,
                float* __restrict__ Cf, __nv_bfloat16* __restrict__ Cs,
                int K, int N, int Kout) {
    extern __shared__ char smc[];
    const uint32_t sb = smem_to_u32(smc);
    const int tid = threadIdx.x, wid = tid >> 5, lane = tid & 31;
    const int bm = blockIdx.y * 128, bn = blockIdx.x * 128;
    const int K2 = 2 * K;
    const int NCk = K >> 6;
    const int NC = 3 * NCk;
    const int mbase = (wid & 1) * 64;
    const int nbase = (wid >> 1) * 64;

    float acc[4][8][4];
#pragma unroll
    for (int mt = 0; mt < 4; mt++)
#pragma unroll
        for (int ng = 0; ng < 8; ng++)
#pragma unroll
            for (int r = 0; r < 4; r++) acc[mt][ng][r] = 0.f;

    const __nv_bfloat16* Abase = A + (size_t)bm * K2;
    const __nv_bfloat16* Bbase = W + (size_t)bn * K2;

    // prologue: stages 0,1 (NC >= 24 always)
    prefetch_tile(Abase, K2, sb, tid);
    prefetch_tile(Bbase, K2, sb + 16384, tid);
    CP_COMMIT();
    prefetch_tile(Abase + 64, K2, sb + 32768, tid);
    prefetch_tile(Bbase + 64, K2, sb + 49152, tid);
    CP_COMMIT();

    const int lrow8 = (lane & 7) + ((lane >> 3) & 1) * 8;
    const int lkoff = (lane >> 4) * 16;

    int sbuf = 0;
    for (int c = 0; c < NC; c++) {
        if (c + 1 < NC) { CP_WAIT(1); } else { CP_WAIT(0); }
        __syncthreads();

        if (c + 2 < NC) {
            int cn = c + 2;
            int ca = (cn < 2 * NCk) ? cn : (cn - 2 * NCk);
            int cb = (cn < NCk) ? cn : (cn - NCk);
            int ps = sbuf + 2; if (ps >= 3) ps -= 3;
            prefetch_tile(Abase + (size_t)ca * 64, K2, sb + ps * 32768, tid);
            prefetch_tile(Bbase + (size_t)cb * 64, K2, sb + ps * 32768 + 16384, tid);
            CP_COMMIT();
        }

        const uint32_t sA = sb + sbuf * 32768;
        const uint32_t sB = sA + 16384;
#pragma unroll
        for (int s = 0; s < 4; s++) {
            uint32_t af[4][4], bf[4][4];
#pragma unroll
            for (int mt = 0; mt < 4; mt++) {
                int row = mbase + mt * 16 + lrow8;
                LDMATRIX_X4(af[mt], sA + SWZ128(row * 128 + s * 32 + lkoff));
            }
#pragma unroll
            for (int ng2 = 0; ng2 < 4; ng2++) {
                int row = nbase + ng2 * 16 + lrow8;
                LDMATRIX_X4(bf[ng2], sB + SWZ128(row * 128 + s * 32 + lkoff));
            }
#pragma unroll
            for (int mt = 0; mt < 4; mt++)
#pragma unroll
                for (int ng2 = 0; ng2 < 4; ng2++) {
                    mma_bf16(acc[mt][ng2 * 2],     af[mt], bf[ng2][0], bf[ng2][2]);
                    mma_bf16(acc[mt][ng2 * 2 + 1], af[mt], bf[ng2][1], bf[ng2][3]);
                }
        }
        sbuf++; if (sbuf == 3) sbuf = 0;
    }

    // ---- epilogue: direct fragment stores ----
    const int qr = lane >> 2;
    const int qc = (lane & 3) * 2;
#pragma unroll
    for (int mt = 0; mt < 4; mt++) {
#pragma unroll
        for (int ng = 0; ng < 8; ng++) {
            const int col = bn + nbase + ng * 8 + qc;
            const float2 bb = *(const float2*)(bias + col);
#pragma unroll
            for (int half = 0; half < 2; half++) {
                const int row = bm + mbase + mt * 16 + qr + half * 8;
                float v0 = acc[mt][ng][half * 2 + 0] + bb.x;
                float v1 = acc[mt][ng][half * 2 + 1] + bb.y;
                if (EPI == 1) {
                    float2 rv = *(const float2*)(res + (size_t)row * N + col);
                    v0 += rv.x; v1 += rv.y;
                }
                if (EPI == 2) {
                    v0 = gelu_exact(v0);
                    v1 = gelu_exact(v1);
                    __nv_bfloat16 h0 = __float2bfloat16(v0);
                    __nv_bfloat16 h1 = __float2bfloat16(v1);
                    float l0 = v0 - __bfloat162float(h0);
                    float l1 = v1 - __bfloat162float(h1);
                    size_t rb = (size_t)row * (2 * Kout);
                    *(__nv_bfloat162*)(Cs + rb + col) = __nv_bfloat162(h0, h1);
                    *(__nv_bfloat162*)(Cs + rb + Kout + col) =
                        __nv_bfloat162(__float2bfloat16(l0), __float2bfloat16(l1));
                } else {
                    *(float2*)(Cf + (size_t)row * N + col) = make_float2(v0, v1);
                }
            }
        }
    }
}

// ---------------- attention (layers 0-4): one block per (b,h), fp32, split ctx ----------------
#define ATTN_SMEM ((NT * 64 + NT * 64 + NT * 65 + 8 * NT) * (int)sizeof(float))

__global__ void __launch_bounds__(256)
attn_kernel(const float* __restrict__ qkv, __nv_bfloat16* __restrict__ cs) {
    extern __shared__ float sm[];
    float* Qs = sm;
    float* Vs = Qs + NT * 64;
    float* Ks = Vs + NT * 64;
    float* sbuf = Ks + NT * 65;
    int b = blockIdx.x >> 3, h = blockIdx.x & 7;
    const float* base = qkv + (size_t)b * NT * (3 * DIM) + h * HD;
    int tid = threadIdx.x;
    for (int i = tid; i < NT * 64; i += 256) {
        int n = i >> 6, d = i & 63;
        const float* p = base + (size_t)n * (3 * DIM) + d;
        Qs[i] = p[0];
        Ks[n * 65 + d] = p[DIM];
        Vs[i] = p[2 * DIM];
    }
    __syncthreads();
    int wid = tid >> 5, lane = tid & 31;
    float* srow = sbuf + wid * NT;
    const float2* V2 = (const float2*)Vs;

    for (int row = wid; row < NT; row += 8) {
        const float* q = Qs + row * 64;
        float mx = -1e30f;
        for (int m = lane; m < NT; m += 32) {
            const float* kr = Ks + m * 65;
            float s = 0.f;
#pragma unroll
            for (int d = 0; d < 64; d++) s = fmaf(q[d], kr[d], s);
            s *= 0.125f;
            srow[m] = s;
            mx = fmaxf(mx, s);
        }
#pragma unroll
        for (int o = 16; o; o >>= 1) mx = fmaxf(mx, __shfl_xor_sync(0xffffffffu, mx, o));
        float sum = 0.f;
        for (int m = lane; m < NT; m += 32) {
            float e = __expf(srow[m] - mx);
            srow[m] = e;
            sum += e;
        }
#pragma unroll
        for (int o = 16; o; o >>= 1) sum += __shfl_xor_sync(0xffffffffu, sum, o);
        float inv = 1.f / sum;
        __syncwarp();
        float ax = 0.f, ay = 0.f;
        for (int m = 0; m < NT; m++) {
            float p = srow[m];
            float2 v = V2[m * 32 + lane];
            ax = fmaf(p, v.x, ax);
            ay = fmaf(p, v.y, ay);
        }
        size_t rb = (size_t)(b * NT + row) * (2 * DIM);
        int col = h * HD + lane * 2;
        split_store(cs, rb, DIM, col,     ax * inv);
        split_store(cs, rb, DIM, col + 1, ay * inv);
        __syncwarp();
    }
}

// ---------------- attention (last layer): only CLS row per (b,h) ----------------
// kv: [MP2 x 1024] (K cols 0..511, V cols 512..1023); qc: [128 x 512]; csc: split [128 x 1024]
__global__ void __launch_bounds__(256)
attn_last_kernel(const float* __restrict__ kv, const float* __restrict__ qc,
                 __nv_bfloat16* __restrict__ csc) {
    __shared__ float qs[64];
    __shared__ float sc[NT];
    __shared__ float red[8];
    __shared__ float bmax, bsum;
    int b = blockIdx.x >> 3, h = blockIdx.x & 7;
    int tid = threadIdx.x, wid = tid >> 5, lane = tid & 31;
    if (tid < 64) qs[tid] = qc[b * DIM + h * HD + tid];
    __syncthreads();
    float s = -1e30f;
    if (tid < NT) {
        const float* kr = kv + ((size_t)(b * NT + tid)) * 1024 + h * HD;
        float a = 0.f;
#pragma unroll
        for (int d = 0; d < 64; d++) a = fmaf(qs[d], kr[d], a);
        s = a * 0.125f;
    }
    float m = s;
#pragma unroll
    for (int o = 16; o; o >>= 1) m = fmaxf(m, __shfl_xor_sync(0xffffffffu, m, o));
    if (lane == 0) red[wid] = m;
    __syncthreads();
    if (tid == 0) {
        float mm = red[0];
#pragma unroll
        for (int k = 1; k < 8; k++) mm = fmaxf(mm, red[k]);
        bmax = mm;
    }
    __syncthreads();
    float e = (tid < NT) ? __expf(s - bmax) : 0.f;
    if (tid < NT) sc[tid] = e;
    float t = e;
#pragma unroll
    for (int o = 16; o; o >>= 1) t += __shfl_xor_sync(0xffffffffu, t, o);
    if (lane == 0) red[wid] = t;
    __syncthreads();
    if (tid == 0) {
        float ss = 0.f;
#pragma unroll
        for (int k = 0; k < 8; k++) ss += red[k];
        bsum = ss;
    }
    __syncthreads();
    if (tid < 64) {
        const float* vb = kv + (size_t)(b * NT) * 1024 + 512 + h * HD + tid;
        float a = 0.f;
        for (int m2 = 0; m2 < NT; m2++) a = fmaf(sc[m2], vb[(size_t)m2 * 1024], a);
        a /= bsum;
        split_store(csc, (size_t)b * (2 * DIM), DIM, h * HD + tid, a);
    }
}

// ---------------- layernorm: in -> out fp32 + xs split ----------------
__global__ void __launch_bounds__(128)
ln_kernel(const float* __restrict__ in, const float* __restrict__ w,
          const float* __restrict__ bp, float* __restrict__ out,
          __nv_bfloat16* __restrict__ xs) {
    int row = blockIdx.x;
    int t = threadIdx.x;
    float4 v = ((const float4*)(in + (size_t)row * DIM))[t];
    float s  = v.x + v.y + v.z + v.w;
    float sq = v.x * v.x + v.y * v.y + v.z * v.z + v.w * v.w;
#pragma unroll
    for (int o = 16; o; o >>= 1) {
        s  += __shfl_xor_sync(0xffffffffu, s, o);
        sq += __shfl_xor_sync(0xffffffffu, sq, o);
    }
    __shared__ float ss[4], ssq[4];
    int wid = t >> 5, lane = t & 31;
    if (lane == 0) { ss[wid] = s; ssq[wid] = sq; }
    __syncthreads();
    s  = ss[0] + ss[1] + ss[2] + ss[3];
    sq = ssq[0] + ssq[1] + ssq[2] + ssq[3];
    float mean = s * (1.f / 512.f);
    float var  = sq * (1.f / 512.f) - mean * mean;
    float r = rsqrtf(var + 1e-5f);
    float4 wv = ((const float4*)w)[t];
    float4 bv = ((const float4*)bp)[t];
    float4 o;
    o.x = (v.x - mean) * r * wv.x + bv.x;
    o.y = (v.y - mean) * r * wv.y + bv.y;
    o.z = (v.z - mean) * r * wv.z + bv.z;
    o.w = (v.w - mean) * r * wv.w + bv.w;
    ((float4*)(out + (size_t)row * DIM))[t] = o;
    size_t rb = (size_t)row * (2 * DIM);
    int c0 = t * 4;
    split_store(xs, rb, DIM, c0 + 0, o.x);
    split_store(xs, rb, DIM, c0 + 1, o.y);
    split_store(xs, rb, DIM, c0 + 2, o.z);
    split_store(xs, rb, DIM, c0 + 3, o.w);
}

// ---------------- host launcher ----------------
extern "C" void kernel_launch(void* const* d_in, const int* in_sizes, int n_in,
                              void* d_out, int out_size) {
    (void)in_sizes; (void)n_in; (void)out_size;
    const float* img    = (const float*)d_in[0];
    const float* pw     = (const float*)d_in[1];
    const float* pb     = (const float*)d_in[2];
    const float* cls    = (const float*)d_in[3];
    const float* pos    = (const float*)d_in[4];
    const float* ipw    = (const float*)d_in[5];
    const float* ipb    = (const float*)d_in[6];
    const float* opw    = (const float*)d_in[7];
    const float* opb    = (const float*)d_in[8];
    const float* ln1w   = (const float*)d_in[9];
    const float* ln1b   = (const float*)d_in[10];
    const float* fc1w   = (const float*)d_in[11];
    const float* fc1b   = (const float*)d_in[12];
    const float* fc2w   = (const float*)d_in[13];
    const float* fc2b   = (const float*)d_in[14];
    const float* ln2w   = (const float*)d_in[15];
    const float* ln2b   = (const float*)d_in[16];
    float* out = (float*)d_out;

    float *x, *y, *qkv, *emb, *qc, *xc, *yc, *xcf;
    __nv_bfloat16 *xps, *xs, *cs, *hs, *pws, *ipws, *opws, *fc1ws, *fc2ws;
    __nv_bfloat16 *cqs, *csc, *xsc, *hsc;
    cudaGetSymbolAddress((void**)&x,     g_x);
    cudaGetSymbolAddress((void**)&y,     g_y);
    cudaGetSymbolAddress((void**)&qkv,   g_qkv);
    cudaGetSymbolAddress((void**)&emb,   g_emb);
    cudaGetSymbolAddress((void**)&xps,   g_xps);
    cudaGetSymbolAddress((void**)&xs,    g_xs);
    cudaGetSymbolAddress((void**)&cs,    g_cs);
    cudaGetSymbolAddress((void**)&hs,    g_hs);
    cudaGetSymbolAddress((void**)&pws,   g_pws);
    cudaGetSymbolAddress((void**)&ipws,  g_ipws);
    cudaGetSymbolAddress((void**)&opws,  g_opws);
    cudaGetSymbolAddress((void**)&fc1ws, g_fc1ws);
    cudaGetSymbolAddress((void**)&fc2ws, g_fc2ws);
    cudaGetSymbolAddress((void**)&cqs,   g_cqs);
    cudaGetSymbolAddress((void**)&qc,    g_qc);
    cudaGetSymbolAddress((void**)&xc,    g_xc);
    cudaGetSymbolAddress((void**)&csc,   g_csc);
    cudaGetSymbolAddress((void**)&yc,    g_yc);
    cudaGetSymbolAddress((void**)&xcf,   g_xcf);
    cudaGetSymbolAddress((void**)&xsc,   g_xsc);
    cudaGetSymbolAddress((void**)&hsc,   g_hsc);

    cudaFuncSetAttribute(attn_kernel, cudaFuncAttributeMaxDynamicSharedMemorySize, ATTN_SMEM);
    cudaFuncSetAttribute(mma_gemm_kernel<0>, cudaFuncAttributeMaxDynamicSharedMemorySize, GEMM_SMEM_BYTES);
    cudaFuncSetAttribute(mma_gemm_kernel<1>, cudaFuncAttributeMaxDynamicSharedMemorySize, GEMM_SMEM_BYTES);
    cudaFuncSetAttribute(mma_gemm_kernel<2>, cudaFuncAttributeMaxDynamicSharedMemorySize, GEMM_SMEM_BYTES);

    // ---- all weight splits (1 launch) ----
    wsplit_all_kernel<<<(WS_TOTAL + 255) / 256, 256>>>(pw, ipw, opw, fc1w, fc2w,
                                                       pws, ipws, opws, fc1ws, fc2ws);

    // ---- patch embed ----
    {
        int n = T_PAT * CPP;
        patchify_kernel<<<(n + 255) / 256, 256>>>(img, xps);
        mma_gemm_kernel<0><<<dim3(DIM / 128, MP2 / 128), 128, GEMM_SMEM_BYTES>>>(
            xps, pws, pb, nullptr, emb, nullptr, CPP, DIM, 0);
        int m = T_TOK * DIM;
        assemble_kernel<<<(m + 255) / 256, 256>>>(emb, cls, pos, x, xs);
    }

    // ---- layers 0..4: full token set ----
    for (int i = 0; i < 5; i++) {
        const __nv_bfloat16* ipws_i  = ipws  + (size_t)i * 3 * DIM * 2 * DIM;
        const __nv_bfloat16* opws_i  = opws  + (size_t)i * DIM * 2 * DIM;
        const __nv_bfloat16* fc1ws_i = fc1ws + (size_t)i * MLPD * 2 * DIM;
        const __nv_bfloat16* fc2ws_i = fc2ws + (size_t)i * DIM * 2 * MLPD;
        const float* ipb_i  = ipb  + (size_t)i * 3 * DIM;
        const float* opb_i  = opb  + (size_t)i * DIM;
        const float* fc1b_i = fc1b + (size_t)i * MLPD;
        const float* fc2b_i = fc2b + (size_t)i * DIM;

        mma_gemm_kernel<0><<<dim3(3 * DIM / 128, MP2 / 128), 128, GEMM_SMEM_BYTES>>>(
            xs, ipws_i, ipb_i, nullptr, qkv, nullptr, DIM, 3 * DIM, 0);
        attn_kernel<<<B_ * HEADS, 256, ATTN_SMEM>>>(qkv, cs);
        mma_gemm_kernel<1><<<dim3(DIM / 128, MP2 / 128), 128, GEMM_SMEM_BYTES>>>(
            cs, opws_i, opb_i, x, y, nullptr, DIM, DIM, 0);
        ln_kernel<<<T_TOK, 128>>>(y, ln1w + i * DIM, ln1b + i * DIM, x, xs);
        mma_gemm_kernel<2><<<dim3(MLPD / 128, MP2 / 128), 128, GEMM_SMEM_BYTES>>>(
            xs, fc1ws_i, fc1b_i, nullptr, nullptr, hs, DIM, MLPD, MLPD);
        mma_gemm_kernel<1><<<dim3(DIM / 128, MP2 / 128), 128, GEMM_SMEM_BYTES>>>(
            hs, fc2ws_i, fc2b_i, x, y, nullptr, MLPD, DIM, 0);
        ln_kernel<<<T_TOK, 128>>>(y, ln2w + i * DIM, ln2b + i * DIM, x, xs);
    }

    // ---- layer 5: CLS-only path ----
    {
        const int i = 5;
        const __nv_bfloat16* ipws_i  = ipws  + (size_t)i * 3 * DIM * 2 * DIM;
        const __nv_bfloat16* opws_i  = opws  + (size_t)i * DIM * 2 * DIM;
        const __nv_bfloat16* fc1ws_i = fc1ws + (size_t)i * MLPD * 2 * DIM;
        const __nv_bfloat16* fc2ws_i = fc2ws + (size_t)i * DIM * 2 * MLPD;
        const float* ipb_i  = ipb  + (size_t)i * 3 * DIM;
        const float* opb_i  = opb  + (size_t)i * DIM;
        const float* fc1b_i = fc1b + (size_t)i * MLPD;
        const float* fc2b_i = fc2b + (size_t)i * DIM;

        // gather CLS rows (x fp32 + xs split)
        gather_cls_kernel<<<(B_ * DIM + 255) / 256, 256>>>(x, xs, xc, cqs);
        // K,V for all tokens: weight rows 512..1535, N=1024 -> qkv[t*1024 +{K|V}]
        mma_gemm_kernel<0><<<dim3(1024 / 128, MP2 / 128), 128, GEMM_SMEM_BYTES>>>(
            xs, ipws_i + (size_t)512 * 2 * DIM, ipb_i + 512, nullptr, qkv, nullptr,
            DIM, 1024, 0);
        // Q for the 64 CLS rows (padded to 128)
        mma_gemm_kernel<0><<<dim3(DIM / 128, 1), 128, GEMM_SMEM_BYTES>>>(
            cqs, ipws_i, ipb_i, nullptr, qc, nullptr, DIM, DIM, 0);
        // attention: only CLS row per (b,h)
        attn_last_kernel<<<B_ * HEADS, 256>>>(qkv, qc, csc);
        // out-proj on 128 rows + residual
        mma_gemm_kernel<1><<<dim3(DIM / 128, 1), 128, GEMM_SMEM_BYTES>>>(
            csc, opws_i, opb_i, xc, yc, nullptr, DIM, DIM, 0);
        ln_kernel<<<B_, 128>>>(yc, ln1w + i * DIM, ln1b + i * DIM, xcf, xsc);
        mma_gemm_kernel<2><<<dim3(MLPD / 128, 1), 128, GEMM_SMEM_BYTES>>>(
            xsc, fc1ws_i, fc1b_i, nullptr, nullptr, hsc, DIM, MLPD, MLPD);
        mma_gemm_kernel<1><<<dim3(DIM / 128, 1), 128, GEMM_SMEM_BYTES>>>(
            hsc, fc2ws_i, fc2b_i, xcf, yc, nullptr, MLPD, DIM, 0);
        // final LN writes d_out directly (64 rows x 512)
        ln_kernel<<<B_, 128>>>(yc, ln2w + i * DIM, ln2b + i * DIM, out, xsc);
    }
}

// round 7
// speedup vs baseline: 2.6649x; 1.1981x over previous
#include <cuda_runtime.h>
#include <cuda_fp16.h>
#include <cuda.h>
#include <math.h>
#include <stdint.h>

// ---------------- model constants ----------------
#define B_     64
#define NPATCH 196
#define NT     197
#define DIM    512
#define HEADS  8
#define HD     64
#define MLPD   2048
#define CPP    768
#define T_TOK  (B_*NT)      // 12608
#define T_PAT  (B_*NPATCH)  // 12544
#define MP2    12800        // padded rows

// ---------------- helpers ----------------
__device__ __forceinline__ uint32_t smem_to_u32(const void* p) {
    uint32_t a;
    asm("{ .reg .u64 t; cvta.to.shared.u64 t, %1; cvt.u32.u64 %0, t; }" : "=r"(a) : "l"(p));
    return a;
}
#define SWZ128(o) ((o) ^ (((o) >> 3) & 0x70))

__device__ __forceinline__ void cp16(uint32_t dst, const void* src) {
    asm volatile("cp.async.cg.shared.global [%0], [%1], 16;" :: "r"(dst), "l"(src));
}
#define CP_COMMIT() asm volatile("cp.async.commit_group;" ::: "memory")
#define CP_WAIT(n)  asm volatile("cp.async.wait_group %0;" :: "n"(n) : "memory")

#define LDMATRIX_X4(r, addr) \
    asm volatile("ldmatrix.sync.aligned.m8n8.x4.shared.b16 {%0,%1,%2,%3}, [%4];" \
        : "=r"((r)[0]), "=r"((r)[1]), "=r"((r)[2]), "=r"((r)[3]) : "r"(addr))

__device__ __forceinline__ void mma_f16(float* c, const uint32_t* a, uint32_t b0, uint32_t b1) {
    asm volatile(
        "mma.sync.aligned.m16n8k16.row.col.f32.f16.f16.f32 "
        "{%0,%1,%2,%3}, {%4,%5,%6,%7}, {%8,%9}, {%0,%1,%2,%3};"
        : "+f"(c[0]), "+f"(c[1]), "+f"(c[2]), "+f"(c[3])
        : "r"(a[0]), "r"(a[1]), "r"(a[2]), "r"(a[3]), "r"(b0), "r"(b1));
}

// ---------------- scratch (device globals: zero-init, allocation-free) ----------------
__device__ float g_x   [MP2 * DIM];
__device__ float g_y   [MP2 * DIM];
__device__ float g_qkv [MP2 * 3 * DIM];
__device__ float g_emb [MP2 * DIM];
// activations: split [hi|lo] fp16, 2K per row
__device__ __align__(16) __half g_xps  [MP2 * 2 * CPP];
__device__ __align__(16) __half g_xs   [MP2 * 2 * DIM];
__device__ __align__(16) __half g_cs   [MP2 * 2 * DIM];
__device__ __align__(16) __half g_hs   [MP2 * 2 * MLPD];
// weights: hi only, K per row
__device__ __align__(16) __half g_pws  [DIM * CPP];
__device__ __align__(16) __half g_ipws [6 * 3 * DIM * DIM];
__device__ __align__(16) __half g_opws [6 * DIM * DIM];
__device__ __align__(16) __half g_fc1ws[6 * MLPD * DIM];
__device__ __align__(16) __half g_fc2ws[6 * DIM * MLPD];
// ---- CLS-path buffers ----
__device__ __align__(16) __half g_cqs [128 * 2 * DIM];
__device__ float g_qc  [128 * DIM];
__device__ float g_xc  [128 * DIM];
__device__ __align__(16) __half g_csc [128 * 2 * DIM];
__device__ float g_yc  [128 * DIM];
__device__ float g_xcf [128 * DIM];
__device__ __align__(16) __half g_xsc [128 * 2 * DIM];
__device__ __align__(16) __half g_hsc [128 * 2 * MLPD];

__device__ __forceinline__ void split_store(__half* dst, size_t rb, int K, int c, float v) {
    __half hi = __float2half_rn(v);
    float lo = v - __half2float(hi);
    dst[rb + c]     = hi;
    dst[rb + K + c] = __float2half_rn(lo);
}

// ---------------- weight convert (hi only) in one launch ----------------
#define WS1 (DIM * CPP)
#define WS2 (6 * 3 * DIM * DIM)
#define WS3 (6 * DIM * DIM)
#define WS4 (6 * MLPD * DIM)
#define WS5 (6 * DIM * MLPD)
#define WS_TOTAL (WS1 + WS2 + WS3 + WS4 + WS5)

__global__ void wsplit_all_kernel(const float* __restrict__ pw, const float* __restrict__ ipw,
                                  const float* __restrict__ opw, const float* __restrict__ fc1w,
                                  const float* __restrict__ fc2w,
                                  __half* __restrict__ pws, __half* __restrict__ ipws,
                                  __half* __restrict__ opws, __half* __restrict__ fc1ws,
                                  __half* __restrict__ fc2ws) {
    int idx = blockIdx.x * blockDim.x + threadIdx.x;
    if (idx >= WS_TOTAL) return;
    const float* src; __half* dst;
    if (idx < WS1)               { src = pw;   dst = pws;   }
    else if ((idx -= WS1) < WS2) { src = ipw;  dst = ipws;  }
    else if ((idx -= WS2) < WS3) { src = opw;  dst = opws;  }
    else if ((idx -= WS3) < WS4) { src = fc1w; dst = fc1ws; }
    else { idx -= WS4;             src = fc2w; dst = fc2ws; }
    dst[idx] = __float2half_rn(src[idx]);
}

__global__ void patchify_kernel(const float* __restrict__ img, __half* __restrict__ xps) {
    int idx = blockIdx.x * blockDim.x + threadIdx.x;
    if (idx >= T_PAT * CPP) return;
    int f   = idx % CPP;
    int row = idx / CPP;
    int b = row / NPATCH, p = row % NPATCH;
    int gh = p / 14, gw = p % 14;
    int c  = f % 3;
    int pp = f / 3;
    int p1 = pp >> 4, p2 = pp & 15;
    float v = img[(((size_t)(b * 3 + c)) * 224 + gh * 16 + p1) * 224 + gw * 16 + p2];
    split_store(xps, (size_t)row * (2 * CPP), CPP, f, v);
}

__global__ void assemble_kernel(const float* __restrict__ emb,
                                const float* __restrict__ cls,
                                const float* __restrict__ pos,
                                float* __restrict__ x, __half* __restrict__ xs) {
    int idx = blockIdx.x * blockDim.x + threadIdx.x;
    if (idx >= T_TOK * DIM) return;
    int d = idx & (DIM - 1);
    int t = idx >> 9;
    int b = t / NT, n = t % NT;
    float v = (n == 0) ? cls[d] : emb[((size_t)(b * NPATCH + n - 1)) * DIM + d];
    v += pos[n * DIM + d];
    x[idx] = v;
    split_store(xs, (size_t)t * (2 * DIM), DIM, d, v);
}

__global__ void gather_cls_kernel(const float* __restrict__ x, const __half* __restrict__ xs,
                                  float* __restrict__ xc, __half* __restrict__ cqs) {
    int idx = blockIdx.x * blockDim.x + threadIdx.x;
    if (idx >= B_ * DIM) return;
    int b = idx >> 9, d = idx & (DIM - 1);
    size_t srow = (size_t)b * NT;
    xc[idx] = x[srow * DIM + d];
    cqs[(size_t)b * 2 * DIM + d]       = xs[srow * 2 * DIM + d];
    cqs[(size_t)b * 2 * DIM + DIM + d] = xs[srow * 2 * DIM + DIM + d];
}

__device__ __forceinline__ float gelu_exact(float v) {
    return 0.5f * v * (1.0f + erff(v * 0.70710678118654752f));
}

// =====================================================================
// HMMA GEMM: C[M,N] = (Ahi+Alo)[M,K] @ Whi[N,K]^T, fp16 2-term split.
// A rows: 2K fp16 ([hi|lo]); W rows: K fp16 (hi only).
// Virtual chunks NC = 2K/64; A chunk ca=c; B chunk cb = c mod (K/64).
// CTA 128x128, 128 thr, 4 warps m64 x n64, 3-stage cp.async ring, 2 CTA/SM.
// EPI 0: fp32 bias   1: fp32 bias+res   2: split-fp16 gelu(bias+acc)
// =====================================================================
#define GEMM_SMEM_BYTES 98304   // 3 stages x (16KB A + 16KB B)

__device__ __forceinline__ void prefetch_tile(const __half* __restrict__ G,
                                              int strideE, uint32_t sbase, int tid) {
#pragma unroll
    for (int r = 0; r < 8; r++) {
        int i = tid + r * 128;
        int row = i >> 3, seg = i & 7;
        cp16(sbase + SWZ128(row * 128 + seg * 16), G + (size_t)row * strideE + seg * 8);
    }
}

template <int EPI>
__global__ void __launch_bounds__(128, 2)
mma_gemm_kernel(const __half* __restrict__ A, const __half* __restrict__ W,
                const float* __restrict__ bias, const float* __restrict__ res,
                float* __restrict__ Cf, __half* __restrict__ Cs,
                int K, int N, int Kout) {
    extern __shared__ char smc[];
    const uint32_t sb = smem_to_u32(smc);
    const int tid = threadIdx.x, wid = tid >> 5, lane = tid & 31;
    const int bm = blockIdx.y * 128, bn = blockIdx.x * 128;
    const int sA_stride = 2 * K;       // A rows are [hi|lo]
    const int NCk = K >> 6;
    const int NC = 2 * NCk;
    const int mbase = (wid & 1) * 64;
    const int nbase = (wid >> 1) * 64;

    float acc[4][8][4];
#pragma unroll
    for (int mt = 0; mt < 4; mt++)
#pragma unroll
        for (int ng = 0; ng < 8; ng++)
#pragma unroll
            for (int r = 0; r < 4; r++) acc[mt][ng][r] = 0.f;

    const __half* Abase = A + (size_t)bm * sA_stride;
    const __half* Bbase = W + (size_t)bn * K;

    // prologue: stages 0,1 (NC >= 16 always)
    prefetch_tile(Abase, sA_stride, sb, tid);
    prefetch_tile(Bbase, K, sb + 16384, tid);
    CP_COMMIT();
    prefetch_tile(Abase + 64, sA_stride, sb + 32768, tid);
    prefetch_tile(Bbase + 64, K, sb + 49152, tid);
    CP_COMMIT();

    const int lrow8 = (lane & 7) + ((lane >> 3) & 1) * 8;
    const int lkoff = (lane >> 4) * 16;

    int sbuf = 0;
    for (int c = 0; c < NC; c++) {
        if (c + 1 < NC) { CP_WAIT(1); } else { CP_WAIT(0); }
        __syncthreads();

        if (c + 2 < NC) {
            int cn = c + 2;
            int cb = (cn < NCk) ? cn : (cn - NCk);
            int ps = sbuf + 2; if (ps >= 3) ps -= 3;
            prefetch_tile(Abase + (size_t)cn * 64, sA_stride, sb + ps * 32768, tid);
            prefetch_tile(Bbase + (size_t)cb * 64, K, sb + ps * 32768 + 16384, tid);
            CP_COMMIT();
        }

        const uint32_t sA = sb + sbuf * 32768;
        const uint32_t sB = sA + 16384;
#pragma unroll
        for (int s = 0; s < 4; s++) {
            uint32_t af[4][4], bf[4][4];
#pragma unroll
            for (int mt = 0; mt < 4; mt++) {
                int row = mbase + mt * 16 + lrow8;
                LDMATRIX_X4(af[mt], sA + SWZ128(row * 128 + s * 32 + lkoff));
            }
#pragma unroll
            for (int ng2 = 0; ng2 < 4; ng2++) {
                int row = nbase + ng2 * 16 + lrow8;
                LDMATRIX_X4(bf[ng2], sB + SWZ128(row * 128 + s * 32 + lkoff));
            }
#pragma unroll
            for (int mt = 0; mt < 4; mt++)
#pragma unroll
                for (int ng2 = 0; ng2 < 4; ng2++) {
                    mma_f16(acc[mt][ng2 * 2],     af[mt], bf[ng2][0], bf[ng2][2]);
                    mma_f16(acc[mt][ng2 * 2 + 1], af[mt], bf[ng2][1], bf[ng2][3]);
                }
        }
        sbuf++; if (sbuf == 3) sbuf = 0;
    }

    // ---- epilogue: direct fragment stores ----
    const int qr = lane >> 2;
    const int qc = (lane & 3) * 2;
#pragma unroll
    for (int mt = 0; mt < 4; mt++) {
#pragma unroll
        for (int ng = 0; ng < 8; ng++) {
            const int col = bn + nbase + ng * 8 + qc;
            const float2 bb = *(const float2*)(bias + col);
#pragma unroll
            for (int half = 0; half < 2; half++) {
                const int row = bm + mbase + mt * 16 + qr + half * 8;
                float v0 = acc[mt][ng][half * 2 + 0] + bb.x;
                float v1 = acc[mt][ng][half * 2 + 1] + bb.y;
                if (EPI == 1) {
                    float2 rv = *(const float2*)(res + (size_t)row * N + col);
                    v0 += rv.x; v1 += rv.y;
                }
                if (EPI == 2) {
                    v0 = gelu_exact(v0);
                    v1 = gelu_exact(v1);
                    __half h0 = __float2half_rn(v0);
                    __half h1 = __float2half_rn(v1);
                    float l0 = v0 - __half2float(h0);
                    float l1 = v1 - __half2float(h1);
                    size_t rb = (size_t)row * (2 * Kout);
                    *(__half2*)(Cs + rb + col) = __half2(h0, h1);
                    *(__half2*)(Cs + rb + Kout + col) =
                        __half2(__float2half_rn(l0), __float2half_rn(l1));
                } else {
                    *(float2*)(Cf + (size_t)row * N + col) = make_float2(v0, v1);
                }
            }
        }
    }
}

// ---------------- attention (layers 0-4): one block per (b,h), fp32, split ctx ----------------
#define ATTN_SMEM ((NT * 64 + NT * 64 + NT * 65 + 8 * NT) * (int)sizeof(float))

__global__ void __launch_bounds__(256)
attn_kernel(const float* __restrict__ qkv, __half* __restrict__ cs) {
    extern __shared__ float sm[];
    float* Qs = sm;
    float* Vs = Qs + NT * 64;
    float* Ks = Vs + NT * 64;
    float* sbuf = Ks + NT * 65;
    int b = blockIdx.x >> 3, h = blockIdx.x & 7;
    const float* base = qkv + (size_t)b * NT * (3 * DIM) + h * HD;
    int tid = threadIdx.x;
    for (int i = tid; i < NT * 64; i += 256) {
        int n = i >> 6, d = i & 63;
        const float* p = base + (size_t)n * (3 * DIM) + d;
        Qs[i] = p[0];
        Ks[n * 65 + d] = p[DIM];
        Vs[i] = p[2 * DIM];
    }
    __syncthreads();
    int wid = tid >> 5, lane = tid & 31;
    float* srow = sbuf + wid * NT;
    const float2* V2 = (const float2*)Vs;

    for (int row = wid; row < NT; row += 8) {
        const float* q = Qs + row * 64;
        float mx = -1e30f;
        for (int m = lane; m < NT; m += 32) {
            const float* kr = Ks + m * 65;
            float s = 0.f;
#pragma unroll
            for (int d = 0; d < 64; d++) s = fmaf(q[d], kr[d], s);
            s *= 0.125f;
            srow[m] = s;
            mx = fmaxf(mx, s);
        }
#pragma unroll
        for (int o = 16; o; o >>= 1) mx = fmaxf(mx, __shfl_xor_sync(0xffffffffu, mx, o));
        float sum = 0.f;
        for (int m = lane; m < NT; m += 32) {
            float e = __expf(srow[m] - mx);
            srow[m] = e;
            sum += e;
        }
#pragma unroll
        for (int o = 16; o; o >>= 1) sum += __shfl_xor_sync(0xffffffffu, sum, o);
        float inv = 1.f / sum;
        __syncwarp();
        float ax = 0.f, ay = 0.f;
        for (int m = 0; m < NT; m++) {
            float p = srow[m];
            float2 v = V2[m * 32 + lane];
            ax = fmaf(p, v.x, ax);
            ay = fmaf(p, v.y, ay);
        }
        size_t rb = (size_t)(b * NT + row) * (2 * DIM);
        int col = h * HD + lane * 2;
        split_store(cs, rb, DIM, col,     ax * inv);
        split_store(cs, rb, DIM, col + 1, ay * inv);
        __syncwarp();
    }
}

// ---------------- attention (last layer): only CLS row per (b,h) ----------------
__global__ void __launch_bounds__(256)
attn_last_kernel(const float* __restrict__ kv, const float* __restrict__ qc,
                 __half* __restrict__ csc) {
    __shared__ float qs[64];
    __shared__ float sc[NT];
    __shared__ float red[8];
    __shared__ float bmax, bsum;
    int b = blockIdx.x >> 3, h = blockIdx.x & 7;
    int tid = threadIdx.x, wid = tid >> 5, lane = tid & 31;
    if (tid < 64) qs[tid] = qc[b * DIM + h * HD + tid];
    __syncthreads();
    float s = -1e30f;
    if (tid < NT) {
        const float* kr = kv + ((size_t)(b * NT + tid)) * 1024 + h * HD;
        float a = 0.f;
#pragma unroll
        for (int d = 0; d < 64; d++) a = fmaf(qs[d], kr[d], a);
        s = a * 0.125f;
    }
    float m = s;
#pragma unroll
    for (int o = 16; o; o >>= 1) m = fmaxf(m, __shfl_xor_sync(0xffffffffu, m, o));
    if (lane == 0) red[wid] = m;
    __syncthreads();
    if (tid == 0) {
        float mm = red[0];
#pragma unroll
        for (int k = 1; k < 8; k++) mm = fmaxf(mm, red[k]);
        bmax = mm;
    }
    __syncthreads();
    float e = (tid < NT) ? __expf(s - bmax) : 0.f;
    if (tid < NT) sc[tid] = e;
    float t = e;
#pragma unroll
    for (int o = 16; o; o >>= 1) t += __shfl_xor_sync(0xffffffffu, t, o);
    if (lane == 0) red[wid] = t;
    __syncthreads();
    if (tid == 0) {
        float ss = 0.f;
#pragma unroll
        for (int k = 0; k < 8; k++) ss += red[k];
        bsum = ss;
    }
    __syncthreads();
    if (tid < 64) {
        const float* vb = kv + (size_t)(b * NT) * 1024 + 512 + h * HD + tid;
        float a = 0.f;
        for (int m2 = 0; m2 < NT; m2++) a = fmaf(sc[m2], vb[(size_t)m2 * 1024], a);
        a /= bsum;
        split_store(csc, (size_t)b * (2 * DIM), DIM, h * HD + tid, a);
    }
}

// ---------------- layernorm: in -> out fp32 + xs split ----------------
__global__ void __launch_bounds__(128)
ln_kernel(const float* __restrict__ in, const float* __restrict__ w,
          const float* __restrict__ bp, float* __restrict__ out,
          __half* __restrict__ xs) {
    int row = blockIdx.x;
    int t = threadIdx.x;
    float4 v = ((const float4*)(in + (size_t)row * DIM))[t];
    float s  = v.x + v.y + v.z + v.w;
    float sq = v.x * v.x + v.y * v.y + v.z * v.z + v.w * v.w;
#pragma unroll
    for (int o = 16; o; o >>= 1) {
        s  += __shfl_xor_sync(0xffffffffu, s, o);
        sq += __shfl_xor_sync(0xffffffffu, sq, o);
    }
    __shared__ float ss[4], ssq[4];
    int wid = t >> 5, lane = t & 31;
    if (lane == 0) { ss[wid] = s; ssq[wid] = sq; }
    __syncthreads();
    s  = ss[0] + ss[1] + ss[2] + ss[3];
    sq = ssq[0] + ssq[1] + ssq[2] + ssq[3];
    float mean = s * (1.f / 512.f);
    float var  = sq * (1.f / 512.f) - mean * mean;
    float r = rsqrtf(var + 1e-5f);
    float4 wv = ((const float4*)w)[t];
    float4 bv = ((const float4*)bp)[t];
    float4 o;
    o.x = (v.x - mean) * r * wv.x + bv.x;
    o.y = (v.y - mean) * r * wv.y + bv.y;
    o.z = (v.z - mean) * r * wv.z + bv.z;
    o.w = (v.w - mean) * r * wv.w + bv.w;
    ((float4*)(out + (size_t)row * DIM))[t] = o;
    size_t rb = (size_t)row * (2 * DIM);
    int c0 = t * 4;
    split_store(xs, rb, DIM, c0 + 0, o.x);
    split_store(xs, rb, DIM, c0 + 1, o.y);
    split_store(xs, rb, DIM, c0 + 2, o.z);
    split_store(xs, rb, DIM, c0 + 3, o.w);
}

// ---------------- host launcher ----------------
extern "C" void kernel_launch(void* const* d_in, const int* in_sizes, int n_in,
                              void* d_out, int out_size) {
    (void)in_sizes; (void)n_in; (void)out_size;
    const float* img    = (const float*)d_in[0];
    const float* pw     = (const float*)d_in[1];
    const float* pb     = (const float*)d_in[2];
    const float* cls    = (const float*)d_in[3];
    const float* pos    = (const float*)d_in[4];
    const float* ipw    = (const float*)d_in[5];
    const float* ipb    = (const float*)d_in[6];
    const float* opw    = (const float*)d_in[7];
    const float* opb    = (const float*)d_in[8];
    const float* ln1w   = (const float*)d_in[9];
    const float* ln1b   = (const float*)d_in[10];
    const float* fc1w   = (const float*)d_in[11];
    const float* fc1b   = (const float*)d_in[12];
    const float* fc2w   = (const float*)d_in[13];
    const float* fc2b   = (const float*)d_in[14];
    const float* ln2w   = (const float*)d_in[15];
    const float* ln2b   = (const float*)d_in[16];
    float* out = (float*)d_out;

    float *x, *y, *qkv, *emb, *qc, *xc, *yc, *xcf;
    __half *xps, *xs, *cs, *hs, *pws, *ipws, *opws, *fc1ws, *fc2ws;
    __half *cqs, *csc, *xsc, *hsc;
    cudaGetSymbolAddress((void**)&x,     g_x);
    cudaGetSymbolAddress((void**)&y,     g_y);
    cudaGetSymbolAddress((void**)&qkv,   g_qkv);
    cudaGetSymbolAddress((void**)&emb,   g_emb);
    cudaGetSymbolAddress((void**)&xps,   g_xps);
    cudaGetSymbolAddress((void**)&xs,    g_xs);
    cudaGetSymbolAddress((void**)&cs,    g_cs);
    cudaGetSymbolAddress((void**)&hs,    g_hs);
    cudaGetSymbolAddress((void**)&pws,   g_pws);
    cudaGetSymbolAddress((void**)&ipws,  g_ipws);
    cudaGetSymbolAddress((void**)&opws,  g_opws);
    cudaGetSymbolAddress((void**)&fc1ws, g_fc1ws);
    cudaGetSymbolAddress((void**)&fc2ws, g_fc2ws);
    cudaGetSymbolAddress((void**)&cqs,   g_cqs);
    cudaGetSymbolAddress((void**)&qc,    g_qc);
    cudaGetSymbolAddress((void**)&xc,    g_xc);
    cudaGetSymbolAddress((void**)&csc,   g_csc);
    cudaGetSymbolAddress((void**)&yc,    g_yc);
    cudaGetSymbolAddress((void**)&xcf,   g_xcf);
    cudaGetSymbolAddress((void**)&xsc,   g_xsc);
    cudaGetSymbolAddress((void**)&hsc,   g_hsc);

    cudaFuncSetAttribute(attn_kernel, cudaFuncAttributeMaxDynamicSharedMemorySize, ATTN_SMEM);
    cudaFuncSetAttribute(mma_gemm_kernel<0>, cudaFuncAttributeMaxDynamicSharedMemorySize, GEMM_SMEM_BYTES);
    cudaFuncSetAttribute(mma_gemm_kernel<1>, cudaFuncAttributeMaxDynamicSharedMemorySize, GEMM_SMEM_BYTES);
    cudaFuncSetAttribute(mma_gemm_kernel<2>, cudaFuncAttributeMaxDynamicSharedMemorySize, GEMM_SMEM_BYTES);

    // ---- weight convert (1 launch) ----
    wsplit_all_kernel<<<(WS_TOTAL + 255) / 256, 256>>>(pw, ipw, opw, fc1w, fc2w,
                                                       pws, ipws, opws, fc1ws, fc2ws);

    // ---- patch embed ----
    {
        int n = T_PAT * CPP;
        patchify_kernel<<<(n + 255) / 256, 256>>>(img, xps);
        mma_gemm_kernel<0><<<dim3(DIM / 128, MP2 / 128), 128, GEMM_SMEM_BYTES>>>(
            xps, pws, pb, nullptr, emb, nullptr, CPP, DIM, 0);
        int m = T_TOK * DIM;
        assemble_kernel<<<(m + 255) / 256, 256>>>(emb, cls, pos, x, xs);
    }

    // ---- layers 0..4: full token set ----
    for (int i = 0; i < 5; i++) {
        const __half* ipws_i  = ipws  + (size_t)i * 3 * DIM * DIM;
        const __half* opws_i  = opws  + (size_t)i * DIM * DIM;
        const __half* fc1ws_i = fc1ws + (size_t)i * MLPD * DIM;
        const __half* fc2ws_i = fc2ws + (size_t)i * DIM * MLPD;
        const float* ipb_i  = ipb  + (size_t)i * 3 * DIM;
        const float* opb_i  = opb  + (size_t)i * DIM;
        const float* fc1b_i = fc1b + (size_t)i * MLPD;
        const float* fc2b_i = fc2b + (size_t)i * DIM;

        mma_gemm_kernel<0><<<dim3(3 * DIM / 128, MP2 / 128), 128, GEMM_SMEM_BYTES>>>(
            xs, ipws_i, ipb_i, nullptr, qkv, nullptr, DIM, 3 * DIM, 0);
        attn_kernel<<<B_ * HEADS, 256, ATTN_SMEM>>>(qkv, cs);
        mma_gemm_kernel<1><<<dim3(DIM / 128, MP2 / 128), 128, GEMM_SMEM_BYTES>>>(
            cs, opws_i, opb_i, x, y, nullptr, DIM, DIM, 0);
        ln_kernel<<<T_TOK, 128>>>(y, ln1w + i * DIM, ln1b + i * DIM, x, xs);
        mma_gemm_kernel<2><<<dim3(MLPD / 128, MP2 / 128), 128, GEMM_SMEM_BYTES>>>(
            xs, fc1ws_i, fc1b_i, nullptr, nullptr, hs, DIM, MLPD, MLPD);
        mma_gemm_kernel<1><<<dim3(DIM / 128, MP2 / 128), 128, GEMM_SMEM_BYTES>>>(
            hs, fc2ws_i, fc2b_i, x, y, nullptr, MLPD, DIM, 0);
        ln_kernel<<<T_TOK, 128>>>(y, ln2w + i * DIM, ln2b + i * DIM, x, xs);
    }

    // ---- layer 5: CLS-only path ----
    {
        const int i = 5;
        const __half* ipws_i  = ipws  + (size_t)i * 3 * DIM * DIM;
        const __half* opws_i  = opws  + (size_t)i * DIM * DIM;
        const __half* fc1ws_i = fc1ws + (size_t)i * MLPD * DIM;
        const __half* fc2ws_i = fc2ws + (size_t)i * DIM * MLPD;
        const float* ipb_i  = ipb  + (size_t)i * 3 * DIM;
        const float* opb_i  = opb  + (size_t)i * DIM;
        const float* fc1b_i = fc1b + (size_t)i * MLPD;
        const float* fc2b_i = fc2b + (size_t)i * DIM;

        gather_cls_kernel<<<(B_ * DIM + 255) / 256, 256>>>(x, xs, xc, cqs);
        // K,V for all tokens: weight rows 512..1535 -> qkv[t*1024 + {K|V}]
        mma_gemm_kernel<0><<<dim3(1024 / 128, MP2 / 128), 128, GEMM_SMEM_BYTES>>>(
            xs, ipws_i + (size_t)512 * DIM, ipb_i + 512, nullptr, qkv, nullptr,
            DIM, 1024, 0);
        // Q for the 64 CLS rows (padded to 128)
        mma_gemm_kernel<0><<<dim3(DIM / 128, 1), 128, GEMM_SMEM_BYTES>>>(
            cqs, ipws_i, ipb_i, nullptr, qc, nullptr, DIM, DIM, 0);
        attn_last_kernel<<<B_ * HEADS, 256>>>(qkv, qc, csc);
        mma_gemm_kernel<1><<<dim3(DIM / 128, 1), 128, GEMM_SMEM_BYTES>>>(
            csc, opws_i, opb_i, xc, yc, nullptr, DIM, DIM, 0);
        ln_kernel<<<B_, 128>>>(yc, ln1w + i * DIM, ln1b + i * DIM, xcf, xsc);
        mma_gemm_kernel<2><<<dim3(MLPD / 128, 1), 128, GEMM_SMEM_BYTES>>>(
            xsc, fc1ws_i, fc1b_i, nullptr, nullptr, hsc, DIM, MLPD, MLPD);
        mma_gemm_kernel<1><<<dim3(DIM / 128, 1), 128, GEMM_SMEM_BYTES>>>(
            hsc, fc2ws_i, fc2b_i, xcf, yc, nullptr, MLPD, DIM, 0);
        ln_kernel<<<B_, 128>>>(yc, ln2w + i * DIM, ln2b + i * DIM, out, xsc);
    }
}

// round 8
// speedup vs baseline: 3.4379x; 1.2901x over previous
#include <cuda_runtime.h>
#include <cuda_fp16.h>
#include <cuda.h>
#include <math.h>
#include <stdint.h>

// ---------------- model constants ----------------
#define B_     64
#define NPATCH 196
#define NT     197
#define DIM    512
#define HEADS  8
#define HD     64
#define MLPD   2048
#define CPP    768
#define T_TOK  (B_*NT)      // 12608
#define T_PAT  (B_*NPATCH)  // 12544
#define MP2    12800        // padded rows

// ---------------- helpers ----------------
__device__ __forceinline__ uint32_t smem_to_u32(const void* p) {
    uint32_t a;
    asm("{ .reg .u64 t; cvta.to.shared.u64 t, %1; cvt.u32.u64 %0, t; }" : "=r"(a) : "l"(p));
    return a;
}
#define SWZ128(o) ((o) ^ (((o) >> 3) & 0x70))

__device__ __forceinline__ void cp16(uint32_t dst, const void* src) {
    asm volatile("cp.async.cg.shared.global [%0], [%1], 16;" :: "r"(dst), "l"(src));
}
#define CP_COMMIT() asm volatile("cp.async.commit_group;" ::: "memory")
#define CP_WAIT(n)  asm volatile("cp.async.wait_group %0;" :: "n"(n) : "memory")

#define LDMATRIX_X4(r, addr) \
    asm volatile("ldmatrix.sync.aligned.m8n8.x4.shared.b16 {%0,%1,%2,%3}, [%4];" \
        : "=r"((r)[0]), "=r"((r)[1]), "=r"((r)[2]), "=r"((r)[3]) : "r"(addr))

__device__ __forceinline__ void mma_f16(float* c, const uint32_t* a, uint32_t b0, uint32_t b1) {
    asm volatile(
        "mma.sync.aligned.m16n8k16.row.col.f32.f16.f16.f32 "
        "{%0,%1,%2,%3}, {%4,%5,%6,%7}, {%8,%9}, {%0,%1,%2,%3};"
        : "+f"(c[0]), "+f"(c[1]), "+f"(c[2]), "+f"(c[3])
        : "r"(a[0]), "r"(a[1]), "r"(a[2]), "r"(a[3]), "r"(b0), "r"(b1));
}

// ---------------- scratch (device globals: zero-init, allocation-free) ----------------
__device__ float g_x   [MP2 * DIM];
__device__ float g_y   [MP2 * DIM];
__device__ float g_qkv [MP2 * 3 * DIM];
__device__ float g_emb [MP2 * DIM];
// activations: plain fp16, K per row
__device__ __align__(16) __half g_xps  [MP2 * CPP];
__device__ __align__(16) __half g_xs   [MP2 * DIM];
__device__ __align__(16) __half g_cs   [MP2 * DIM];
__device__ __align__(16) __half g_hs   [MP2 * MLPD];
// weights: plain fp16
__device__ __align__(16) __half g_pws  [DIM * CPP];
__device__ __align__(16) __half g_ipws [6 * 3 * DIM * DIM];
__device__ __align__(16) __half g_opws [6 * DIM * DIM];
__device__ __align__(16) __half g_fc1ws[6 * MLPD * DIM];
__device__ __align__(16) __half g_fc2ws[6 * DIM * MLPD];
// ---- CLS-path buffers ----
__device__ __align__(16) __half g_cqs [128 * DIM];
__device__ float g_qc  [128 * DIM];
__device__ float g_xc  [128 * DIM];
__device__ __align__(16) __half g_csc [128 * DIM];
__device__ float g_yc  [128 * DIM];
__device__ float g_xcf [128 * DIM];
__device__ __align__(16) __half g_xsc [128 * DIM];
__device__ __align__(16) __half g_hsc [128 * MLPD];

// ---------------- weight convert in one launch ----------------
#define WS1 (DIM * CPP)
#define WS2 (6 * 3 * DIM * DIM)
#define WS3 (6 * DIM * DIM)
#define WS4 (6 * MLPD * DIM)
#define WS5 (6 * DIM * MLPD)
#define WS_TOTAL (WS1 + WS2 + WS3 + WS4 + WS5)

__global__ void wsplit_all_kernel(const float* __restrict__ pw, const float* __restrict__ ipw,
                                  const float* __restrict__ opw, const float* __restrict__ fc1w,
                                  const float* __restrict__ fc2w,
                                  __half* __restrict__ pws, __half* __restrict__ ipws,
                                  __half* __restrict__ opws, __half* __restrict__ fc1ws,
                                  __half* __restrict__ fc2ws) {
    int idx = blockIdx.x * blockDim.x + threadIdx.x;
    if (idx >= WS_TOTAL) return;
    const float* src; __half* dst;
    if (idx < WS1)               { src = pw;   dst = pws;   }
    else if ((idx -= WS1) < WS2) { src = ipw;  dst = ipws;  }
    else if ((idx -= WS2) < WS3) { src = opw;  dst = opws;  }
    else if ((idx -= WS3) < WS4) { src = fc1w; dst = fc1ws; }
    else { idx -= WS4;             src = fc2w; dst = fc2ws; }
    dst[idx] = __float2half_rn(src[idx]);
}

__global__ void patchify_kernel(const float* __restrict__ img, __half* __restrict__ xps) {
    int idx = blockIdx.x * blockDim.x + threadIdx.x;
    if (idx >= T_PAT * CPP) return;
    int f   = idx % CPP;
    int row = idx / CPP;
    int b = row / NPATCH, p = row % NPATCH;
    int gh = p / 14, gw = p % 14;
    int c  = f % 3;
    int pp = f / 3;
    int p1 = pp >> 4, p2 = pp & 15;
    float v = img[(((size_t)(b * 3 + c)) * 224 + gh * 16 + p1) * 224 + gw * 16 + p2];
    xps[(size_t)row * CPP + f] = __float2half_rn(v);
}

__global__ void assemble_kernel(const float* __restrict__ emb,
                                const float* __restrict__ cls,
                                const float* __restrict__ pos,
                                float* __restrict__ x, __half* __restrict__ xs) {
    int idx = blockIdx.x * blockDim.x + threadIdx.x;
    if (idx >= T_TOK * DIM) return;
    int d = idx & (DIM - 1);
    int t = idx >> 9;
    int b = t / NT, n = t % NT;
    float v = (n == 0) ? cls[d] : emb[((size_t)(b * NPATCH + n - 1)) * DIM + d];
    v += pos[n * DIM + d];
    x[idx] = v;
    xs[idx] = __float2half_rn(v);
}

__global__ void gather_cls_kernel(const float* __restrict__ x, const __half* __restrict__ xs,
                                  float* __restrict__ xc, __half* __restrict__ cqs) {
    int idx = blockIdx.x * blockDim.x + threadIdx.x;
    if (idx >= B_ * DIM) return;
    int b = idx >> 9, d = idx & (DIM - 1);
    size_t srow = (size_t)b * NT;
    xc[idx]  = x[srow * DIM + d];
    cqs[idx] = xs[srow * DIM + d];
}

__device__ __forceinline__ float gelu_exact(float v) {
    return 0.5f * v * (1.0f + erff(v * 0.70710678118654752f));
}

// =====================================================================
// HMMA GEMM: C[M,N] = A[M,K] @ W[N,K]^T, plain fp16, fp32 accum.
// CTA 128x128, 128 thr, 4 warps m64 x n64, BK=64 chunks,
// 3-stage cp.async ring, one sync per chunk, 2 CTA/SM.
// EPI 0: fp32 bias   1: fp32 bias+res   2: fp16 gelu(bias+acc), row stride Kout
// =====================================================================
#define GEMM_SMEM_BYTES 98304   // 3 stages x (16KB A + 16KB B)

__device__ __forceinline__ void prefetch_tile(const __half* __restrict__ G,
                                              int strideE, uint32_t sbase, int tid) {
#pragma unroll
    for (int r = 0; r < 8; r++) {
        int i = tid + r * 128;
        int row = i >> 3, seg = i & 7;
        cp16(sbase + SWZ128(row * 128 + seg * 16), G + (size_t)row * strideE + seg * 8);
    }
}

template <int EPI>
__global__ void __launch_bounds__(128, 2)
mma_gemm_kernel(const __half* __restrict__ A, const __half* __restrict__ W,
                const float* __restrict__ bias, const float* __restrict__ res,
                float* __restrict__ Cf, __half* __restrict__ Cs,
                int K, int N, int Kout) {
    extern __shared__ char smc[];
    const uint32_t sb = smem_to_u32(smc);
    const int tid = threadIdx.x, wid = tid >> 5, lane = tid & 31;
    const int bm = blockIdx.y * 128, bn = blockIdx.x * 128;
    const int NC = K >> 6;
    const int mbase = (wid & 1) * 64;
    const int nbase = (wid >> 1) * 64;

    float acc[4][8][4];
#pragma unroll
    for (int mt = 0; mt < 4; mt++)
#pragma unroll
        for (int ng = 0; ng < 8; ng++)
#pragma unroll
            for (int r = 0; r < 4; r++) acc[mt][ng][r] = 0.f;

    const __half* Abase = A + (size_t)bm * K;
    const __half* Bbase = W + (size_t)bn * K;

    // prologue: stages 0,1 (NC >= 8 always)
    prefetch_tile(Abase, K, sb, tid);
    prefetch_tile(Bbase, K, sb + 16384, tid);
    CP_COMMIT();
    prefetch_tile(Abase + 64, K, sb + 32768, tid);
    prefetch_tile(Bbase + 64, K, sb + 49152, tid);
    CP_COMMIT();

    const int lrow8 = (lane & 7) + ((lane >> 3) & 1) * 8;
    const int lkoff = (lane >> 4) * 16;

    int sbuf = 0;
    for (int c = 0; c < NC; c++) {
        if (c + 1 < NC) { CP_WAIT(1); } else { CP_WAIT(0); }
        __syncthreads();

        if (c + 2 < NC) {
            int cn = c + 2;
            int ps = sbuf + 2; if (ps >= 3) ps -= 3;
            prefetch_tile(Abase + (size_t)cn * 64, K, sb + ps * 32768, tid);
            prefetch_tile(Bbase + (size_t)cn * 64, K, sb + ps * 32768 + 16384, tid);
            CP_COMMIT();
        }

        const uint32_t sA = sb + sbuf * 32768;
        const uint32_t sB = sA + 16384;
#pragma unroll
        for (int s = 0; s < 4; s++) {
            uint32_t af[4][4], bf[4][4];
#pragma unroll
            for (int mt = 0; mt < 4; mt++) {
                int row = mbase + mt * 16 + lrow8;
                LDMATRIX_X4(af[mt], sA + SWZ128(row * 128 + s * 32 + lkoff));
            }
#pragma unroll
            for (int ng2 = 0; ng2 < 4; ng2++) {
                int row = nbase + ng2 * 16 + lrow8;
                LDMATRIX_X4(bf[ng2], sB + SWZ128(row * 128 + s * 32 + lkoff));
            }
#pragma unroll
            for (int mt = 0; mt < 4; mt++)
#pragma unroll
                for (int ng2 = 0; ng2 < 4; ng2++) {
                    mma_f16(acc[mt][ng2 * 2],     af[mt], bf[ng2][0], bf[ng2][2]);
                    mma_f16(acc[mt][ng2 * 2 + 1], af[mt], bf[ng2][1], bf[ng2][3]);
                }
        }
        sbuf++; if (sbuf == 3) sbuf = 0;
    }

    // ---- epilogue: direct fragment stores ----
    const int qr = lane >> 2;
    const int qc = (lane & 3) * 2;
#pragma unroll
    for (int mt = 0; mt < 4; mt++) {
#pragma unroll
        for (int ng = 0; ng < 8; ng++) {
            const int col = bn + nbase + ng * 8 + qc;
            const float2 bb = *(const float2*)(bias + col);
#pragma unroll
            for (int half = 0; half < 2; half++) {
                const int row = bm + mbase + mt * 16 + qr + half * 8;
                float v0 = acc[mt][ng][half * 2 + 0] + bb.x;
                float v1 = acc[mt][ng][half * 2 + 1] + bb.y;
                if (EPI == 1) {
                    float2 rv = *(const float2*)(res + (size_t)row * N + col);
                    v0 += rv.x; v1 += rv.y;
                }
                if (EPI == 2) {
                    v0 = gelu_exact(v0);
                    v1 = gelu_exact(v1);
                    *(__half2*)(Cs + (size_t)row * Kout + col) =
                        __half2(__float2half_rn(v0), __float2half_rn(v1));
                } else {
                    *(float2*)(Cf + (size_t)row * N + col) = make_float2(v0, v1);
                }
            }
        }
    }
}

// ---------------- attention (layers 0-4): one block per (b,h), fp32, fp16 ctx ----------------
#define ATTN_SMEM ((NT * 64 + NT * 64 + NT * 65 + 8 * NT) * (int)sizeof(float))

__global__ void __launch_bounds__(256)
attn_kernel(const float* __restrict__ qkv, __half* __restrict__ cs) {
    extern __shared__ float sm[];
    float* Qs = sm;
    float* Vs = Qs + NT * 64;
    float* Ks = Vs + NT * 64;
    float* sbuf = Ks + NT * 65;
    int b = blockIdx.x >> 3, h = blockIdx.x & 7;
    const float* base = qkv + (size_t)b * NT * (3 * DIM) + h * HD;
    int tid = threadIdx.x;
    for (int i = tid; i < NT * 64; i += 256) {
        int n = i >> 6, d = i & 63;
        const float* p = base + (size_t)n * (3 * DIM) + d;
        Qs[i] = p[0];
        Ks[n * 65 + d] = p[DIM];
        Vs[i] = p[2 * DIM];
    }
    __syncthreads();
    int wid = tid >> 5, lane = tid & 31;
    float* srow = sbuf + wid * NT;
    const float2* V2 = (const float2*)Vs;

    for (int row = wid; row < NT; row += 8) {
        const float* q = Qs + row * 64;
        float mx = -1e30f;
        for (int m = lane; m < NT; m += 32) {
            const float* kr = Ks + m * 65;
            float s = 0.f;
#pragma unroll
            for (int d = 0; d < 64; d++) s = fmaf(q[d], kr[d], s);
            s *= 0.125f;
            srow[m] = s;
            mx = fmaxf(mx, s);
        }
#pragma unroll
        for (int o = 16; o; o >>= 1) mx = fmaxf(mx, __shfl_xor_sync(0xffffffffu, mx, o));
        float sum = 0.f;
        for (int m = lane; m < NT; m += 32) {
            float e = __expf(srow[m] - mx);
            srow[m] = e;
            sum += e;
        }
#pragma unroll
        for (int o = 16; o; o >>= 1) sum += __shfl_xor_sync(0xffffffffu, sum, o);
        float inv = 1.f / sum;
        __syncwarp();
        float ax = 0.f, ay = 0.f;
        for (int m = 0; m < NT; m++) {
            float p = srow[m];
            float2 v = V2[m * 32 + lane];
            ax = fmaf(p, v.x, ax);
            ay = fmaf(p, v.y, ay);
        }
        size_t rb = (size_t)(b * NT + row) * DIM;
        int col = h * HD + lane * 2;
        *(__half2*)(cs + rb + col) =
            __half2(__float2half_rn(ax * inv), __float2half_rn(ay * inv));
        __syncwarp();
    }
}

// ---------------- attention (last layer): only CLS row per (b,h) ----------------
__global__ void __launch_bounds__(256)
attn_last_kernel(const float* __restrict__ kv, const float* __restrict__ qc,
                 __half* __restrict__ csc) {
    __shared__ float qs[64];
    __shared__ float sc[NT];
    __shared__ float red[8];
    __shared__ float bmax, bsum;
    int b = blockIdx.x >> 3, h = blockIdx.x & 7;
    int tid = threadIdx.x, wid = tid >> 5, lane = tid & 31;
    if (tid < 64) qs[tid] = qc[b * DIM + h * HD + tid];
    __syncthreads();
    float s = -1e30f;
    if (tid < NT) {
        const float* kr = kv + ((size_t)(b * NT + tid)) * 1024 + h * HD;
        float a = 0.f;
#pragma unroll
        for (int d = 0; d < 64; d++) a = fmaf(qs[d], kr[d], a);
        s = a * 0.125f;
    }
    float m = s;
#pragma unroll
    for (int o = 16; o; o >>= 1) m = fmaxf(m, __shfl_xor_sync(0xffffffffu, m, o));
    if (lane == 0) red[wid] = m;
    __syncthreads();
    if (tid == 0) {
        float mm = red[0];
#pragma unroll
        for (int k = 1; k < 8; k++) mm = fmaxf(mm, red[k]);
        bmax = mm;
    }
    __syncthreads();
    float e = (tid < NT) ? __expf(s - bmax) : 0.f;
    if (tid < NT) sc[tid] = e;
    float t = e;
#pragma unroll
    for (int o = 16; o; o >>= 1) t += __shfl_xor_sync(0xffffffffu, t, o);
    if (lane == 0) red[wid] = t;
    __syncthreads();
    if (tid == 0) {
        float ss = 0.f;
#pragma unroll
        for (int k = 0; k < 8; k++) ss += red[k];
        bsum = ss;
    }
    __syncthreads();
    if (tid < 64) {
        const float* vb = kv + (size_t)(b * NT) * 1024 + 512 + h * HD + tid;
        float a = 0.f;
        for (int m2 = 0; m2 < NT; m2++) a = fmaf(sc[m2], vb[(size_t)m2 * 1024], a);
        a /= bsum;
        csc[(size_t)b * DIM + h * HD + tid] = __float2half_rn(a);
    }
}

// ---------------- layernorm: in -> out fp32 + xs fp16 ----------------
__global__ void __launch_bounds__(128)
ln_kernel(const float* __restrict__ in, const float* __restrict__ w,
          const float* __restrict__ bp, float* __restrict__ out,
          __half* __restrict__ xs) {
    int row = blockIdx.x;
    int t = threadIdx.x;
    float4 v = ((const float4*)(in + (size_t)row * DIM))[t];
    float s  = v.x + v.y + v.z + v.w;
    float sq = v.x * v.x + v.y * v.y + v.z * v.z + v.w * v.w;
#pragma unroll
    for (int o = 16; o; o >>= 1) {
        s  += __shfl_xor_sync(0xffffffffu, s, o);
        sq += __shfl_xor_sync(0xffffffffu, sq, o);
    }
    __shared__ float ss[4], ssq[4];
    int wid = t >> 5, lane = t & 31;
    if (lane == 0) { ss[wid] = s; ssq[wid] = sq; }
    __syncthreads();
    s  = ss[0] + ss[1] + ss[2] + ss[3];
    sq = ssq[0] + ssq[1] + ssq[2] + ssq[3];
    float mean = s * (1.f / 512.f);
    float var  = sq * (1.f / 512.f) - mean * mean;
    float r = rsqrtf(var + 1e-5f);
    float4 wv = ((const float4*)w)[t];
    float4 bv = ((const float4*)bp)[t];
    float4 o;
    o.x = (v.x - mean) * r * wv.x + bv.x;
    o.y = (v.y - mean) * r * wv.y + bv.y;
    o.z = (v.z - mean) * r * wv.z + bv.z;
    o.w = (v.w - mean) * r * wv.w + bv.w;
    ((float4*)(out + (size_t)row * DIM))[t] = o;
    __half2 h01 = __half2(__float2half_rn(o.x), __float2half_rn(o.y));
    __half2 h23 = __half2(__float2half_rn(o.z), __float2half_rn(o.w));
    *(__half2*)(xs + (size_t)row * DIM + t * 4)     = h01;
    *(__half2*)(xs + (size_t)row * DIM + t * 4 + 2) = h23;
}

// ---------------- host launcher ----------------
extern "C" void kernel_launch(void* const* d_in, const int* in_sizes, int n_in,
                              void* d_out, int out_size) {
    (void)in_sizes; (void)n_in; (void)out_size;
    const float* img    = (const float*)d_in[0];
    const float* pw     = (const float*)d_in[1];
    const float* pb     = (const float*)d_in[2];
    const float* cls    = (const float*)d_in[3];
    const float* pos    = (const float*)d_in[4];
    const float* ipw    = (const float*)d_in[5];
    const float* ipb    = (const float*)d_in[6];
    const float* opw    = (const float*)d_in[7];
    const float* opb    = (const float*)d_in[8];
    const float* ln1w   = (const float*)d_in[9];
    const float* ln1b   = (const float*)d_in[10];
    const float* fc1w   = (const float*)d_in[11];
    const float* fc1b   = (const float*)d_in[12];
    const float* fc2w   = (const float*)d_in[13];
    const float* fc2b   = (const float*)d_in[14];
    const float* ln2w   = (const float*)d_in[15];
    const float* ln2b   = (const float*)d_in[16];
    float* out = (float*)d_out;

    float *x, *y, *qkv, *emb, *qc, *xc, *yc, *xcf;
    __half *xps, *xs, *cs, *hs, *pws, *ipws, *opws, *fc1ws, *fc2ws;
    __half *cqs, *csc, *xsc, *hsc;
    cudaGetSymbolAddress((void**)&x,     g_x);
    cudaGetSymbolAddress((void**)&y,     g_y);
    cudaGetSymbolAddress((void**)&qkv,   g_qkv);
    cudaGetSymbolAddress((void**)&emb,   g_emb);
    cudaGetSymbolAddress((void**)&xps,   g_xps);
    cudaGetSymbolAddress((void**)&xs,    g_xs);
    cudaGetSymbolAddress((void**)&cs,    g_cs);
    cudaGetSymbolAddress((void**)&hs,    g_hs);
    cudaGetSymbolAddress((void**)&pws,   g_pws);
    cudaGetSymbolAddress((void**)&ipws,  g_ipws);
    cudaGetSymbolAddress((void**)&opws,  g_opws);
    cudaGetSymbolAddress((void**)&fc1ws, g_fc1ws);
    cudaGetSymbolAddress((void**)&fc2ws, g_fc2ws);
    cudaGetSymbolAddress((void**)&cqs,   g_cqs);
    cudaGetSymbolAddress((void**)&qc,    g_qc);
    cudaGetSymbolAddress((void**)&xc,    g_xc);
    cudaGetSymbolAddress((void**)&csc,   g_csc);
    cudaGetSymbolAddress((void**)&yc,    g_yc);
    cudaGetSymbolAddress((void**)&xcf,   g_xcf);
    cudaGetSymbolAddress((void**)&xsc,   g_xsc);
    cudaGetSymbolAddress((void**)&hsc,   g_hsc);

    cudaFuncSetAttribute(attn_kernel, cudaFuncAttributeMaxDynamicSharedMemorySize, ATTN_SMEM);
    cudaFuncSetAttribute(mma_gemm_kernel<0>, cudaFuncAttributeMaxDynamicSharedMemorySize, GEMM_SMEM_BYTES);
    cudaFuncSetAttribute(mma_gemm_kernel<1>, cudaFuncAttributeMaxDynamicSharedMemorySize, GEMM_SMEM_BYTES);
    cudaFuncSetAttribute(mma_gemm_kernel<2>, cudaFuncAttributeMaxDynamicSharedMemorySize, GEMM_SMEM_BYTES);

    // ---- weight convert (1 launch) ----
    wsplit_all_kernel<<<(WS_TOTAL + 255) / 256, 256>>>(pw, ipw, opw, fc1w, fc2w,
                                                       pws, ipws, opws, fc1ws, fc2ws);

    // ---- patch embed ----
    {
        int n = T_PAT * CPP;
        patchify_kernel<<<(n + 255) / 256, 256>>>(img, xps);
        mma_gemm_kernel<0><<<dim3(DIM / 128, MP2 / 128), 128, GEMM_SMEM_BYTES>>>(
            xps, pws, pb, nullptr, emb, nullptr, CPP, DIM, 0);
        int m = T_TOK * DIM;
        assemble_kernel<<<(m + 255) / 256, 256>>>(emb, cls, pos, x, xs);
    }

    // ---- layers 0..4: full token set ----
    for (int i = 0; i < 5; i++) {
        const __half* ipws_i  = ipws  + (size_t)i * 3 * DIM * DIM;
        const __half* opws_i  = opws  + (size_t)i * DIM * DIM;
        const __half* fc1ws_i = fc1ws + (size_t)i * MLPD * DIM;
        const __half* fc2ws_i = fc2ws + (size_t)i * DIM * MLPD;
        const float* ipb_i  = ipb  + (size_t)i * 3 * DIM;
        const float* opb_i  = opb  + (size_t)i * DIM;
        const float* fc1b_i = fc1b + (size_t)i * MLPD;
        const float* fc2b_i = fc2b + (size_t)i * DIM;

        mma_gemm_kernel<0><<<dim3(3 * DIM / 128, MP2 / 128), 128, GEMM_SMEM_BYTES>>>(
            xs, ipws_i, ipb_i, nullptr, qkv, nullptr, DIM, 3 * DIM, 0);
        attn_kernel<<<B_ * HEADS, 256, ATTN_SMEM>>>(qkv, cs);
        mma_gemm_kernel<1><<<dim3(DIM / 128, MP2 / 128), 128, GEMM_SMEM_BYTES>>>(
            cs, opws_i, opb_i, x, y, nullptr, DIM, DIM, 0);
        ln_kernel<<<T_TOK, 128>>>(y, ln1w + i * DIM, ln1b + i * DIM, x, xs);
        mma_gemm_kernel<2><<<dim3(MLPD / 128, MP2 / 128), 128, GEMM_SMEM_BYTES>>>(
            xs, fc1ws_i, fc1b_i, nullptr, nullptr, hs, DIM, MLPD, MLPD);
        mma_gemm_kernel<1><<<dim3(DIM / 128, MP2 / 128), 128, GEMM_SMEM_BYTES>>>(
            hs, fc2ws_i, fc2b_i, x, y, nullptr, MLPD, DIM, 0);
        ln_kernel<<<T_TOK, 128>>>(y, ln2w + i * DIM, ln2b + i * DIM, x, xs);
    }

    // ---- layer 5: CLS-only path ----
    {
        const int i = 5;
        const __half* ipws_i  = ipws  + (size_t)i * 3 * DIM * DIM;
        const __half* opws_i  = opws  + (size_t)i * DIM * DIM;
        const __half* fc1ws_i = fc1ws + (size_t)i * MLPD * DIM;
        const __half* fc2ws_i = fc2ws + (size_t)i * DIM * MLPD;
        const float* ipb_i  = ipb  + (size_t)i * 3 * DIM;
        const float* opb_i  = opb  + (size_t)i * DIM;
        const float* fc1b_i = fc1b + (size_t)i * MLPD;
        const float* fc2b_i = fc2b + (size_t)i * DIM;

        gather_cls_kernel<<<(B_ * DIM + 255) / 256, 256>>>(x, xs, xc, cqs);
        // K,V for all tokens: weight rows 512..1535 -> qkv[t*1024 + {K|V}]
        mma_gemm_kernel<0><<<dim3(1024 / 128, MP2 / 128), 128, GEMM_SMEM_BYTES>>>(
            xs, ipws_i + (size_t)512 * DIM, ipb_i + 512, nullptr, qkv, nullptr,
            DIM, 1024, 0);
        // Q for the 64 CLS rows (padded to 128)
        mma_gemm_kernel<0><<<dim3(DIM / 128, 1), 128, GEMM_SMEM_BYTES>>>(
            cqs, ipws_i, ipb_i, nullptr, qc, nullptr, DIM, DIM, 0);
        attn_last_kernel<<<B_ * HEADS, 256>>>(qkv, qc, csc);
        mma_gemm_kernel<1><<<dim3(DIM / 128, 1), 128, GEMM_SMEM_BYTES>>>(
            csc, opws_i, opb_i, xc, yc, nullptr, DIM, DIM, 0);
        ln_kernel<<<B_, 128>>>(yc, ln1w + i * DIM, ln1b + i * DIM, xcf, xsc);
        mma_gemm_kernel<2><<<dim3(MLPD / 128, 1), 128, GEMM_SMEM_BYTES>>>(
            xsc, fc1ws_i, fc1b_i, nullptr, nullptr, hsc, DIM, MLPD, MLPD);
        mma_gemm_kernel<1><<<dim3(DIM / 128, 1), 128, GEMM_SMEM_BYTES>>>(
            hsc, fc2ws_i, fc2b_i, xcf, yc, nullptr, MLPD, DIM, 0);
        ln_kernel<<<B_, 128>>>(yc, ln2w + i * DIM, ln2b + i * DIM, out, xsc);
    }
}

// round 9
// speedup vs baseline: 4.3406x; 1.2626x over previous
#include <cuda_runtime.h>
#include <cuda_fp16.h>
#include <cuda.h>
#include <math.h>
#include <stdint.h>

// ---------------- model constants ----------------
#define B_     64
#define NPATCH 196
#define NT     197
#define DIM    512
#define HEADS  8
#define HD     64
#define MLPD   2048
#define CPP    768
#define T_TOK  (B_*NT)      // 12608
#define T_PAT  (B_*NPATCH)  // 12544
#define MP2    12800        // padded rows
#define GEMM_MAX_GRID 296   // 2 CTAs x 148 SMs

// ---------------- helpers ----------------
__device__ __forceinline__ uint32_t smem_to_u32(const void* p) {
    uint32_t a;
    asm("{ .reg .u64 t; cvta.to.shared.u64 t, %1; cvt.u32.u64 %0, t; }" : "=r"(a) : "l"(p));
    return a;
}
#define SWZ128(o) ((o) ^ (((o) >> 3) & 0x70))

__device__ __forceinline__ void cp16(uint32_t dst, const void* src) {
    asm volatile("cp.async.cg.shared.global [%0], [%1], 16;" :: "r"(dst), "l"(src));
}
#define CP_COMMIT() asm volatile("cp.async.commit_group;" ::: "memory")
#define CP_WAIT(n)  asm volatile("cp.async.wait_group %0;" :: "n"(n) : "memory")

#define LDMATRIX_X4(r, addr) \
    asm volatile("ldmatrix.sync.aligned.m8n8.x4.shared.b16 {%0,%1,%2,%3}, [%4];" \
        : "=r"((r)[0]), "=r"((r)[1]), "=r"((r)[2]), "=r"((r)[3]) : "r"(addr))

__device__ __forceinline__ void mma_f16(float* c, const uint32_t* a, uint32_t b0, uint32_t b1) {
    asm volatile(
        "mma.sync.aligned.m16n8k16.row.col.f32.f16.f16.f32 "
        "{%0,%1,%2,%3}, {%4,%5,%6,%7}, {%8,%9}, {%0,%1,%2,%3};"
        : "+f"(c[0]), "+f"(c[1]), "+f"(c[2]), "+f"(c[3])
        : "r"(a[0]), "r"(a[1]), "r"(a[2]), "r"(a[3]), "r"(b0), "r"(b1));
}

// ---------------- scratch (device globals: zero-init, allocation-free) ----------------
__device__ float g_x   [MP2 * DIM];
__device__ float g_y   [MP2 * DIM];
__device__ float g_emb [MP2 * DIM];
__device__ __align__(16) __half g_qkv [MP2 * 3 * DIM];   // fp16 now
// activations: plain fp16
__device__ __align__(16) __half g_xps  [MP2 * CPP];
__device__ __align__(16) __half g_xs   [MP2 * DIM];
__device__ __align__(16) __half g_cs   [MP2 * DIM];
__device__ __align__(16) __half g_hs   [MP2 * MLPD];
// weights: plain fp16
__device__ __align__(16) __half g_pws  [DIM * CPP];
__device__ __align__(16) __half g_ipws [6 * 3 * DIM * DIM];
__device__ __align__(16) __half g_opws [6 * DIM * DIM];
__device__ __align__(16) __half g_fc1ws[6 * MLPD * DIM];
__device__ __align__(16) __half g_fc2ws[6 * DIM * MLPD];
// ---- CLS-path buffers ----
__device__ __align__(16) __half g_cqs [128 * DIM];
__device__ float g_qc  [128 * DIM];
__device__ float g_xc  [128 * DIM];
__device__ __align__(16) __half g_csc [128 * DIM];
__device__ float g_yc  [128 * DIM];
__device__ float g_xcf [128 * DIM];
__device__ __align__(16) __half g_xsc [128 * DIM];
__device__ __align__(16) __half g_hsc [128 * MLPD];

// ---------------- weight convert in one launch ----------------
#define WS1 (DIM * CPP)
#define WS2 (6 * 3 * DIM * DIM)
#define WS3 (6 * DIM * DIM)
#define WS4 (6 * MLPD * DIM)
#define WS5 (6 * DIM * MLPD)
#define WS_TOTAL (WS1 + WS2 + WS3 + WS4 + WS5)

__global__ void wsplit_all_kernel(const float* __restrict__ pw, const float* __restrict__ ipw,
                                  const float* __restrict__ opw, const float* __restrict__ fc1w,
                                  const float* __restrict__ fc2w,
                                  __half* __restrict__ pws, __half* __restrict__ ipws,
                                  __half* __restrict__ opws, __half* __restrict__ fc1ws,
                                  __half* __restrict__ fc2ws) {
    int idx = blockIdx.x * blockDim.x + threadIdx.x;
    if (idx >= WS_TOTAL) return;
    const float* src; __half* dst;
    if (idx < WS1)               { src = pw;   dst = pws;   }
    else if ((idx -= WS1) < WS2) { src = ipw;  dst = ipws;  }
    else if ((idx -= WS2) < WS3) { src = opw;  dst = opws;  }
    else if ((idx -= WS3) < WS4) { src = fc1w; dst = fc1ws; }
    else { idx -= WS4;             src = fc2w; dst = fc2ws; }
    dst[idx] = __float2half_rn(src[idx]);
}

__global__ void patchify_kernel(const float* __restrict__ img, __half* __restrict__ xps) {
    int idx = blockIdx.x * blockDim.x + threadIdx.x;
    if (idx >= T_PAT * CPP) return;
    int f   = idx % CPP;
    int row = idx / CPP;
    int b = row / NPATCH, p = row % NPATCH;
    int gh = p / 14, gw = p % 14;
    int c  = f % 3;
    int pp = f / 3;
    int p1 = pp >> 4, p2 = pp & 15;
    float v = img[(((size_t)(b * 3 + c)) * 224 + gh * 16 + p1) * 224 + gw * 16 + p2];
    xps[(size_t)row * CPP + f] = __float2half_rn(v);
}

__global__ void assemble_kernel(const float* __restrict__ emb,
                                const float* __restrict__ cls,
                                const float* __restrict__ pos,
                                float* __restrict__ x, __half* __restrict__ xs) {
    int idx = blockIdx.x * blockDim.x + threadIdx.x;
    if (idx >= T_TOK * DIM) return;
    int d = idx & (DIM - 1);
    int t = idx >> 9;
    int b = t / NT, n = t % NT;
    float v = (n == 0) ? cls[d] : emb[((size_t)(b * NPATCH + n - 1)) * DIM + d];
    v += pos[n * DIM + d];
    x[idx] = v;
    xs[idx] = __float2half_rn(v);
}

__global__ void gather_cls_kernel(const float* __restrict__ x, const __half* __restrict__ xs,
                                  float* __restrict__ xc, __half* __restrict__ cqs) {
    int idx = blockIdx.x * blockDim.x + threadIdx.x;
    if (idx >= B_ * DIM) return;
    int b = idx >> 9, d = idx & (DIM - 1);
    size_t srow = (size_t)b * NT;
    xc[idx]  = x[srow * DIM + d];
    cqs[idx] = xs[srow * DIM + d];
}

__device__ __forceinline__ float gelu_exact(float v) {
    return 0.5f * v * (1.0f + erff(v * 0.70710678118654752f));
}

// =====================================================================
// Persistent HMMA GEMM: C[M,N] = A[M,K] @ W[N,K]^T, fp16, fp32 accum.
// grid-stride over 128x128 tiles; ONE cp.async chunk stream per CTA
// spanning all its tiles (ring never drains; prologue paid once).
// 128 thr, 4 warps m64 x n64, BK=64 chunks, 3-stage ring, 2 CTA/SM.
// EPI 0: fp32 bias  1: fp32 bias+res  2: fp16 gelu (stride Kout)
// EPI 3: fp16 bias (stride N)
// =====================================================================
#define GEMM_SMEM_BYTES 98304   // 3 stages x (16KB A + 16KB B)

__device__ __forceinline__ void prefetch_tile(const __half* __restrict__ G,
                                              int strideE, uint32_t sbase, int tid) {
#pragma unroll
    for (int r = 0; r < 8; r++) {
        int i = tid + r * 128;
        int row = i >> 3, seg = i & 7;
        cp16(sbase + SWZ128(row * 128 + seg * 16), G + (size_t)row * strideE + seg * 8);
    }
}

template <int EPI>
__global__ void __launch_bounds__(128, 2)
mma_gemm_kernel(const __half* __restrict__ A, const __half* __restrict__ W,
                const float* __restrict__ bias, const float* __restrict__ res,
                float* __restrict__ Cf, __half* __restrict__ Cs,
                int K, int N, int Kout, int Ntiles, int total_tiles) {
    extern __shared__ char smc[];
    const uint32_t sb = smem_to_u32(smc);
    const int tid = threadIdx.x, wid = tid >> 5, lane = tid & 31;
    const int NC = K >> 6;
    const int mbase = (wid & 1) * 64;
    const int nbase = (wid >> 1) * 64;
    const int GRID = gridDim.x;

    if (blockIdx.x >= total_tiles) return;
    const int my_tiles = (total_tiles - blockIdx.x + GRID - 1) / GRID;
    const long total_chunks = (long)my_tiles * NC;

    // prefetch-cursor state (tile t_pf, chunk c_pf)
    int t_pf = blockIdx.x, c_pf = 0;
    const __half* Apf = A + (size_t)(t_pf / Ntiles) * 128 * K;
    const __half* Bpf = W + (size_t)(t_pf % Ntiles) * 128 * K;

    auto pf = [&](int stage) {
        if (t_pf < total_tiles) {
            prefetch_tile(Apf + (size_t)c_pf * 64, K, sb + stage * 32768, tid);
            prefetch_tile(Bpf + (size_t)c_pf * 64, K, sb + stage * 32768 + 16384, tid);
        }
        CP_COMMIT();
        if (++c_pf == NC) {
            c_pf = 0;
            t_pf += GRID;
            if (t_pf < total_tiles) {
                Apf = A + (size_t)(t_pf / Ntiles) * 128 * K;
                Bpf = W + (size_t)(t_pf % Ntiles) * 128 * K;
            }
        }
    };

    pf(0);
    pf(1);

    const int lrow8 = (lane & 7) + ((lane >> 3) & 1) * 8;
    const int lkoff = (lane >> 4) * 16;
    const int qr = lane >> 2;
    const int qc = (lane & 3) * 2;

    int sbuf = 0;
    long done = 0;
    float acc[4][8][4];

    for (int t = blockIdx.x; t < total_tiles; t += GRID) {
#pragma unroll
        for (int mt = 0; mt < 4; mt++)
#pragma unroll
            for (int ng = 0; ng < 8; ng++)
#pragma unroll
                for (int r = 0; r < 4; r++) acc[mt][ng][r] = 0.f;

        for (int c = 0; c < NC; c++) {
            if (done + 1 < total_chunks) { CP_WAIT(1); } else { CP_WAIT(0); }
            __syncthreads();

            int ps = sbuf + 2; if (ps >= 3) ps -= 3;
            pf(ps);

            const uint32_t sA = sb + sbuf * 32768;
            const uint32_t sB = sA + 16384;
#pragma unroll
            for (int s = 0; s < 4; s++) {
                uint32_t af[4][4], bf[4][4];
#pragma unroll
                for (int mt = 0; mt < 4; mt++) {
                    int row = mbase + mt * 16 + lrow8;
                    LDMATRIX_X4(af[mt], sA + SWZ128(row * 128 + s * 32 + lkoff));
                }
#pragma unroll
                for (int ng2 = 0; ng2 < 4; ng2++) {
                    int row = nbase + ng2 * 16 + lrow8;
                    LDMATRIX_X4(bf[ng2], sB + SWZ128(row * 128 + s * 32 + lkoff));
                }
#pragma unroll
                for (int mt = 0; mt < 4; mt++)
#pragma unroll
                    for (int ng2 = 0; ng2 < 4; ng2++) {
                        mma_f16(acc[mt][ng2 * 2],     af[mt], bf[ng2][0], bf[ng2][2]);
                        mma_f16(acc[mt][ng2 * 2 + 1], af[mt], bf[ng2][1], bf[ng2][3]);
                    }
            }
            sbuf++; if (sbuf == 3) sbuf = 0;
            done++;
        }

        // ---- epilogue for tile t (register-only; overlaps in-flight prefetch) ----
        const int bm = (t / Ntiles) * 128;
        const int bn = (t % Ntiles) * 128;
#pragma unroll
        for (int mt = 0; mt < 4; mt++) {
#pragma unroll
            for (int ng = 0; ng < 8; ng++) {
                const int col = bn + nbase + ng * 8 + qc;
                const float2 bb = *(const float2*)(bias + col);
#pragma unroll
                for (int half = 0; half < 2; half++) {
                    const int row = bm + mbase + mt * 16 + qr + half * 8;
                    float v0 = acc[mt][ng][half * 2 + 0] + bb.x;
                    float v1 = acc[mt][ng][half * 2 + 1] + bb.y;
                    if (EPI == 1) {
                        float2 rv = *(const float2*)(res + (size_t)row * N + col);
                        v0 += rv.x; v1 += rv.y;
                    }
                    if (EPI == 2) {
                        v0 = gelu_exact(v0);
                        v1 = gelu_exact(v1);
                        *(__half2*)(Cs + (size_t)row * Kout + col) =
                            __half2(__float2half_rn(v0), __float2half_rn(v1));
                    } else if (EPI == 3) {
                        *(__half2*)(Cs + (size_t)row * N + col) =
                            __half2(__float2half_rn(v0), __float2half_rn(v1));
                    } else {
                        *(float2*)(Cf + (size_t)row * N + col) = make_float2(v0, v1);
                    }
                }
            }
        }
    }
}

// ---------------- attention (layers 0-4): one block per (b,h), fp16 K/V, 2 CTA/SM ----------------
// smem: Qs fp32[197*64]=50432 | Vs fp16[197*64]=25216 | Ks fp16[197*66]=26004 | sbuf fp32[8*197]=6304
#define ATTN_SMEM (50432 + 25216 + 26004 + 6304)

__global__ void __launch_bounds__(256, 2)
attn_kernel(const __half* __restrict__ qkv, __half* __restrict__ cs) {
    extern __shared__ char smb[];
    float*  Qs   = (float*)smb;
    __half* Vsh  = (__half*)(smb + 50432);
    __half* Ksh  = (__half*)(smb + 75648);
    float*  sbuf = (float*)(smb + 101652);
    int b = blockIdx.x >> 3, h = blockIdx.x & 7;
    const __half* base = qkv + (size_t)b * NT * (3 * DIM) + h * HD;
    int tid = threadIdx.x;
    for (int i = tid; i < NT * 64; i += 256) {
        int n = i >> 6, d = i & 63;
        const __half* p = base + (size_t)n * (3 * DIM) + d;
        Qs[i] = __half2float(p[0]);
        Ksh[n * 66 + d] = p[DIM];
        Vsh[i] = p[2 * DIM];
    }
    __syncthreads();
    int wid = tid >> 5, lane = tid & 31;
    float* srow = sbuf + wid * NT;
    const __half2* V2h = (const __half2*)Vsh;

    for (int row = wid; row < NT; row += 8) {
        const float* q = Qs + row * 64;
        float mx = -1e30f;
        for (int m = lane; m < NT; m += 32) {
            const __half2* kr = (const __half2*)Ksh + m * 33;
            float s = 0.f;
#pragma unroll
            for (int d2 = 0; d2 < 32; d2++) {
                float2 kf = __half22float2(kr[d2]);
                s = fmaf(q[2 * d2],     kf.x, s);
                s = fmaf(q[2 * d2 + 1], kf.y, s);
            }
            s *= 0.125f;
            srow[m] = s;
            mx = fmaxf(mx, s);
        }
#pragma unroll
        for (int o = 16; o; o >>= 1) mx = fmaxf(mx, __shfl_xor_sync(0xffffffffu, mx, o));
        float sum = 0.f;
        for (int m = lane; m < NT; m += 32) {
            float e = __expf(srow[m] - mx);
            srow[m] = e;
            sum += e;
        }
#pragma unroll
        for (int o = 16; o; o >>= 1) sum += __shfl_xor_sync(0xffffffffu, sum, o);
        float inv = 1.f / sum;
        __syncwarp();
        float ax = 0.f, ay = 0.f;
        for (int m = 0; m < NT; m++) {
            float p = srow[m];
            float2 v = __half22float2(V2h[m * 32 + lane]);
            ax = fmaf(p, v.x, ax);
            ay = fmaf(p, v.y, ay);
        }
        size_t rb = (size_t)(b * NT + row) * DIM;
        int col = h * HD + lane * 2;
        *(__half2*)(cs + rb + col) =
            __half2(__float2half_rn(ax * inv), __float2half_rn(ay * inv));
        __syncwarp();
    }
}

// ---------------- attention (last layer): only CLS row per (b,h), fp16 kv ----------------
__global__ void __launch_bounds__(256)
attn_last_kernel(const __half* __restrict__ kv, const float* __restrict__ qc,
                 __half* __restrict__ csc) {
    __shared__ float qs[64];
    __shared__ float sc[NT];
    __shared__ float red[8];
    __shared__ float bmax, bsum;
    int b = blockIdx.x >> 3, h = blockIdx.x & 7;
    int tid = threadIdx.x, wid = tid >> 5, lane = tid & 31;
    if (tid < 64) qs[tid] = qc[b * DIM + h * HD + tid];
    __syncthreads();
    float s = -1e30f;
    if (tid < NT) {
        const __half* kr = kv + ((size_t)(b * NT + tid)) * 1024 + h * HD;
        float a = 0.f;
#pragma unroll
        for (int d = 0; d < 64; d++) a = fmaf(qs[d], __half2float(kr[d]), a);
        s = a * 0.125f;
    }
    float m = s;
#pragma unroll
    for (int o = 16; o; o >>= 1) m = fmaxf(m, __shfl_xor_sync(0xffffffffu, m, o));
    if (lane == 0) red[wid] = m;
    __syncthreads();
    if (tid == 0) {
        float mm = red[0];
#pragma unroll
        for (int k = 1; k < 8; k++) mm = fmaxf(mm, red[k]);
        bmax = mm;
    }
    __syncthreads();
    float e = (tid < NT) ? __expf(s - bmax) : 0.f;
    if (tid < NT) sc[tid] = e;
    float t = e;
#pragma unroll
    for (int o = 16; o; o >>= 1) t += __shfl_xor_sync(0xffffffffu, t, o);
    if (lane == 0) red[wid] = t;
    __syncthreads();
    if (tid == 0) {
        float ss = 0.f;
#pragma unroll
        for (int k = 0; k < 8; k++) ss += red[k];
        bsum = ss;
    }
    __syncthreads();
    if (tid < 64) {
        const __half* vb = kv + (size_t)(b * NT) * 1024 + 512 + h * HD + tid;
        float a = 0.f;
        for (int m2 = 0; m2 < NT; m2++) a = fmaf(sc[m2], __half2float(vb[(size_t)m2 * 1024]), a);
        a /= bsum;
        csc[(size_t)b * DIM + h * HD + tid] = __float2half_rn(a);
    }
}

// ---------------- layernorm: in -> out fp32 + xs fp16 ----------------
__global__ void __launch_bounds__(128)
ln_kernel(const float* __restrict__ in, const float* __restrict__ w,
          const float* __restrict__ bp, float* __restrict__ out,
          __half* __restrict__ xs) {
    int row = blockIdx.x;
    int t = threadIdx.x;
    float4 v = ((const float4*)(in + (size_t)row * DIM))[t];
    float s  = v.x + v.y + v.z + v.w;
    float sq = v.x * v.x + v.y * v.y + v.z * v.z + v.w * v.w;
#pragma unroll
    for (int o = 16; o; o >>= 1) {
        s  += __shfl_xor_sync(0xffffffffu, s, o);
        sq += __shfl_xor_sync(0xffffffffu, sq, o);
    }
    __shared__ float ss[4], ssq[4];
    int wid = t >> 5, lane = t & 31;
    if (lane == 0) { ss[wid] = s; ssq[wid] = sq; }
    __syncthreads();
    s  = ss[0] + ss[1] + ss[2] + ss[3];
    sq = ssq[0] + ssq[1] + ssq[2] + ssq[3];
    float mean = s * (1.f / 512.f);
    float var  = sq * (1.f / 512.f) - mean * mean;
    float r = rsqrtf(var + 1e-5f);
    float4 wv = ((const float4*)w)[t];
    float4 bv = ((const float4*)bp)[t];
    float4 o;
    o.x = (v.x - mean) * r * wv.x + bv.x;
    o.y = (v.y - mean) * r * wv.y + bv.y;
    o.z = (v.z - mean) * r * wv.z + bv.z;
    o.w = (v.w - mean) * r * wv.w + bv.w;
    ((float4*)(out + (size_t)row * DIM))[t] = o;
    __half2 h01 = __half2(__float2half_rn(o.x), __float2half_rn(o.y));
    __half2 h23 = __half2(__float2half_rn(o.z), __float2half_rn(o.w));
    *(__half2*)(xs + (size_t)row * DIM + t * 4)     = h01;
    *(__half2*)(xs + (size_t)row * DIM + t * 4 + 2) = h23;
}

static inline int gemm_grid(int tiles) { return tiles < GEMM_MAX_GRID ? tiles : GEMM_MAX_GRID; }

// ---------------- host launcher ----------------
extern "C" void kernel_launch(void* const* d_in, const int* in_sizes, int n_in,
                              void* d_out, int out_size) {
    (void)in_sizes; (void)n_in; (void)out_size;
    const float* img    = (const float*)d_in[0];
    const float* pw     = (const float*)d_in[1];
    const float* pb     = (const float*)d_in[2];
    const float* cls    = (const float*)d_in[3];
    const float* pos    = (const float*)d_in[4];
    const float* ipw    = (const float*)d_in[5];
    const float* ipb    = (const float*)d_in[6];
    const float* opw    = (const float*)d_in[7];
    const float* opb    = (const float*)d_in[8];
    const float* ln1w   = (const float*)d_in[9];
    const float* ln1b   = (const float*)d_in[10];
    const float* fc1w   = (const float*)d_in[11];
    const float* fc1b   = (const float*)d_in[12];
    const float* fc2w   = (const float*)d_in[13];
    const float* fc2b   = (const float*)d_in[14];
    const float* ln2w   = (const float*)d_in[15];
    const float* ln2b   = (const float*)d_in[16];
    float* out = (float*)d_out;

    float *x, *y, *emb, *qc, *xc, *yc, *xcf;
    __half *qkvh, *xps, *xs, *cs, *hs, *pws, *ipws, *opws, *fc1ws, *fc2ws;
    __half *cqs, *csc, *xsc, *hsc;
    cudaGetSymbolAddress((void**)&x,     g_x);
    cudaGetSymbolAddress((void**)&y,     g_y);
    cudaGetSymbolAddress((void**)&qkvh,  g_qkv);
    cudaGetSymbolAddress((void**)&emb,   g_emb);
    cudaGetSymbolAddress((void**)&xps,   g_xps);
    cudaGetSymbolAddress((void**)&xs,    g_xs);
    cudaGetSymbolAddress((void**)&cs,    g_cs);
    cudaGetSymbolAddress((void**)&hs,    g_hs);
    cudaGetSymbolAddress((void**)&pws,   g_pws);
    cudaGetSymbolAddress((void**)&ipws,  g_ipws);
    cudaGetSymbolAddress((void**)&opws,  g_opws);
    cudaGetSymbolAddress((void**)&fc1ws, g_fc1ws);
    cudaGetSymbolAddress((void**)&fc2ws, g_fc2ws);
    cudaGetSymbolAddress((void**)&cqs,   g_cqs);
    cudaGetSymbolAddress((void**)&qc,    g_qc);
    cudaGetSymbolAddress((void**)&xc,    g_xc);
    cudaGetSymbolAddress((void**)&csc,   g_csc);
    cudaGetSymbolAddress((void**)&yc,    g_yc);
    cudaGetSymbolAddress((void**)&xcf,   g_xcf);
    cudaGetSymbolAddress((void**)&xsc,   g_xsc);
    cudaGetSymbolAddress((void**)&hsc,   g_hsc);

    cudaFuncSetAttribute(attn_kernel, cudaFuncAttributeMaxDynamicSharedMemorySize, ATTN_SMEM);
    cudaFuncSetAttribute(mma_gemm_kernel<0>, cudaFuncAttributeMaxDynamicSharedMemorySize, GEMM_SMEM_BYTES);
    cudaFuncSetAttribute(mma_gemm_kernel<1>, cudaFuncAttributeMaxDynamicSharedMemorySize, GEMM_SMEM_BYTES);
    cudaFuncSetAttribute(mma_gemm_kernel<2>, cudaFuncAttributeMaxDynamicSharedMemorySize, GEMM_SMEM_BYTES);
    cudaFuncSetAttribute(mma_gemm_kernel<3>, cudaFuncAttributeMaxDynamicSharedMemorySize, GEMM_SMEM_BYTES);

    // ---- weight convert (1 launch) ----
    wsplit_all_kernel<<<(WS_TOTAL + 255) / 256, 256>>>(pw, ipw, opw, fc1w, fc2w,
                                                       pws, ipws, opws, fc1ws, fc2ws);

    // ---- patch embed ----
    {
        int n = T_PAT * CPP;
        patchify_kernel<<<(n + 255) / 256, 256>>>(img, xps);
        int tiles = 4 * 100;
        mma_gemm_kernel<0><<<gemm_grid(tiles), 128, GEMM_SMEM_BYTES>>>(
            xps, pws, pb, nullptr, emb, nullptr, CPP, DIM, 0, 4, tiles);
        int m = T_TOK * DIM;
        assemble_kernel<<<(m + 255) / 256, 256>>>(emb, cls, pos, x, xs);
    }

    // ---- layers 0..4: full token set ----
    for (int i = 0; i < 5; i++) {
        const __half* ipws_i  = ipws  + (size_t)i * 3 * DIM * DIM;
        const __half* opws_i  = opws  + (size_t)i * DIM * DIM;
        const __half* fc1ws_i = fc1ws + (size_t)i * MLPD * DIM;
        const __half* fc2ws_i = fc2ws + (size_t)i * DIM * MLPD;
        const float* ipb_i  = ipb  + (size_t)i * 3 * DIM;
        const float* opb_i  = opb  + (size_t)i * DIM;
        const float* fc1b_i = fc1b + (size_t)i * MLPD;
        const float* fc2b_i = fc2b + (size_t)i * DIM;

        int tq = 12 * 100;
        mma_gemm_kernel<3><<<gemm_grid(tq), 128, GEMM_SMEM_BYTES>>>(
            xs, ipws_i, ipb_i, nullptr, nullptr, qkvh, DIM, 3 * DIM, 0, 12, tq);
        attn_kernel<<<B_ * HEADS, 256, ATTN_SMEM>>>(qkvh, cs);
        int to = 4 * 100;
        mma_gemm_kernel<1><<<gemm_grid(to), 128, GEMM_SMEM_BYTES>>>(
            cs, opws_i, opb_i, x, y, nullptr, DIM, DIM, 0, 4, to);
        ln_kernel<<<T_TOK, 128>>>(y, ln1w + i * DIM, ln1b + i * DIM, x, xs);
        int t1 = 16 * 100;
        mma_gemm_kernel<2><<<gemm_grid(t1), 128, GEMM_SMEM_BYTES>>>(
            xs, fc1ws_i, fc1b_i, nullptr, nullptr, hs, DIM, MLPD, MLPD, 16, t1);
        int t2 = 4 * 100;
        mma_gemm_kernel<1><<<gemm_grid(t2), 128, GEMM_SMEM_BYTES>>>(
            hs, fc2ws_i, fc2b_i, x, y, nullptr, MLPD, DIM, 0, 4, t2);
        ln_kernel<<<T_TOK, 128>>>(y, ln2w + i * DIM, ln2b + i * DIM, x, xs);
    }

    // ---- layer 5: CLS-only path ----
    {
        const int i = 5;
        const __half* ipws_i  = ipws  + (size_t)i * 3 * DIM * DIM;
        const __half* opws_i  = opws  + (size_t)i * DIM * DIM;
        const __half* fc1ws_i = fc1ws + (size_t)i * MLPD * DIM;
        const __half* fc2ws_i = fc2ws + (size_t)i * DIM * MLPD;
        const float* ipb_i  = ipb  + (size_t)i * 3 * DIM;
        const float* opb_i  = opb  + (size_t)i * DIM;
        const float* fc1b_i = fc1b + (size_t)i * MLPD;
        const float* fc2b_i = fc2b + (size_t)i * DIM;

        gather_cls_kernel<<<(B_ * DIM + 255) / 256, 256>>>(x, xs, xc, cqs);
        // K,V for all tokens: weight rows 512..1535 -> qkv[t*1024 + {K|V}], fp16
        int tkv = 8 * 100;
        mma_gemm_kernel<3><<<gemm_grid(tkv), 128, GEMM_SMEM_BYTES>>>(
            xs, ipws_i + (size_t)512 * DIM, ipb_i + 512, nullptr, nullptr, qkvh,
            DIM, 1024, 0, 8, tkv);
        // Q for the 64 CLS rows (padded to 128), fp32
        mma_gemm_kernel<0><<<gemm_grid(4), 128, GEMM_SMEM_BYTES>>>(
            cqs, ipws_i, ipb_i, nullptr, qc, nullptr, DIM, DIM, 0, 4, 4);
        attn_last_kernel<<<B_ * HEADS, 256>>>(qkvh, qc, csc);
        mma_gemm_kernel<1><<<gemm_grid(4), 128, GEMM_SMEM_BYTES>>>(
            csc, opws_i, opb_i, xc, yc, nullptr, DIM, DIM, 0, 4, 4);
        ln_kernel<<<B_, 128>>>(yc, ln1w + i * DIM, ln1b + i * DIM, xcf, xsc);
        mma_gemm_kernel<2><<<gemm_grid(16), 128, GEMM_SMEM_BYTES>>>(
            xsc, fc1ws_i, fc1b_i, nullptr, nullptr, hsc, DIM, MLPD, MLPD, 16, 16);
        mma_gemm_kernel<1><<<gemm_grid(4), 128, GEMM_SMEM_BYTES>>>(
            hsc, fc2ws_i, fc2b_i, xcf, yc, nullptr, MLPD, DIM, 0, 4, 4);
        ln_kernel<<<B_, 128>>>(yc, ln2w + i * DIM, ln2b + i * DIM, out, xsc);
    }
}